// round 2
// baseline (speedup 1.0000x reference)
#include <cuda_runtime.h>

#define MAXN 10000
#define MAXE 320000
#define IN_DIM 512
#define H1 256
#define H2 128

// ---------------- scratch (device globals; no allocation allowed) ----------------
__device__ int   g_deg_out[MAXN];
__device__ int   g_deg_in[MAXN];
__device__ int   g_cnt[MAXN];
__device__ float g_rs_out[MAXN];
__device__ float g_rs_in[MAXN];
__device__ int   g_row_off[MAXN + 1];
__device__ int   g_perm_src[MAXE];
__device__ float g_y1[MAXN * H1];    // (x*rs_out) @ W1
__device__ float g_h[MAXN * H1];     // relu(conv1)
__device__ float g_y23[MAXN * H1];   // (h*rs_out) @ [W2|W3]
__device__ float g_z[MAXN * H2];     // mean + noise*exp(log_std)

// ---------------- small setup kernels ----------------
__global__ void zero_kernel(int n) {
    int i = blockIdx.x * blockDim.x + threadIdx.x;
    if (i < n) { g_deg_out[i] = 0; g_deg_in[i] = 0; g_cnt[i] = 0; }
}

__global__ void degree_kernel(const int* __restrict__ src, const int* __restrict__ dst, int e) {
    int i = blockIdx.x * blockDim.x + threadIdx.x;
    if (i < e) {
        atomicAdd(&g_deg_out[src[i]], 1);
        atomicAdd(&g_deg_in[dst[i]], 1);
    }
}

__global__ void rs_kernel(int n) {
    int i = blockIdx.x * blockDim.x + threadIdx.x;
    if (i < n) {
        g_rs_out[i] = rsqrtf(fmaxf((float)g_deg_out[i], 1.0f));
        g_rs_in[i]  = rsqrtf(fmaxf((float)g_deg_in[i], 1.0f));
    }
}

// single-block exclusive scan of deg_in -> row_off
__global__ void scan_kernel(int n) {
    __shared__ int sh[1024];
    int t = threadIdx.x;
    int carry = 0;
    for (int base = 0; base < n; base += 1024) {
        int v = (base + t < n) ? g_deg_in[base + t] : 0;
        __syncthreads();
        sh[t] = v;
        __syncthreads();
        for (int off = 1; off < 1024; off <<= 1) {
            int x = (t >= off) ? sh[t - off] : 0;
            __syncthreads();
            sh[t] += x;
            __syncthreads();
        }
        if (base + t < n) g_row_off[base + t] = carry + sh[t] - v;
        carry += sh[1023];
    }
    if (t == 0) g_row_off[n] = carry;
}

__global__ void perm_kernel(const int* __restrict__ src, const int* __restrict__ dst, int e) {
    int i = blockIdx.x * blockDim.x + threadIdx.x;
    if (i < e) {
        int d = dst[i];
        int pos = atomicAdd(&g_cnt[d], 1);
        g_perm_src[g_row_off[d] + pos] = src[i];
    }
}

// ---------------- GEMM 1: y1 = (X * rs_out) @ W1   [M,512]x[512,256] ----------------
__global__ void gemm1_kernel(const float* __restrict__ X, const float* __restrict__ W, int M) {
    __shared__ float As[64][17];
    __shared__ float Bs[16][64];
    int tid = threadIdx.x, tx = tid & 15, ty = tid >> 4;
    int m0 = blockIdx.x * 64, n0 = blockIdx.y * 64;
    float acc[4][4] = {};
    for (int k0 = 0; k0 < IN_DIM; k0 += 16) {
#pragma unroll
        for (int q = 0; q < 4; q++) {
            int e = tid + q * 256;
            int r = e >> 4, c = e & 15;
            int row = m0 + r;
            As[r][c] = (row < M) ? X[row * IN_DIM + k0 + c] * g_rs_out[row] : 0.f;
        }
#pragma unroll
        for (int q = 0; q < 4; q++) {
            int e = tid + q * 256;
            int r = e >> 6, c = e & 63;
            Bs[r][c] = W[(k0 + r) * H1 + n0 + c];
        }
        __syncthreads();
#pragma unroll
        for (int k = 0; k < 16; k++) {
            float a0 = As[ty * 4 + 0][k], a1 = As[ty * 4 + 1][k];
            float a2 = As[ty * 4 + 2][k], a3 = As[ty * 4 + 3][k];
            float4 b = *(const float4*)&Bs[k][tx * 4];
            acc[0][0] += a0 * b.x; acc[0][1] += a0 * b.y; acc[0][2] += a0 * b.z; acc[0][3] += a0 * b.w;
            acc[1][0] += a1 * b.x; acc[1][1] += a1 * b.y; acc[1][2] += a1 * b.z; acc[1][3] += a1 * b.w;
            acc[2][0] += a2 * b.x; acc[2][1] += a2 * b.y; acc[2][2] += a2 * b.z; acc[2][3] += a2 * b.w;
            acc[3][0] += a3 * b.x; acc[3][1] += a3 * b.y; acc[3][2] += a3 * b.z; acc[3][3] += a3 * b.w;
        }
        __syncthreads();
    }
#pragma unroll
    for (int ii = 0; ii < 4; ii++) {
        int row = m0 + ty * 4 + ii;
        if (row < M) {
#pragma unroll
            for (int jj = 0; jj < 4; jj++)
                g_y1[row * H1 + n0 + tx * 4 + jj] = acc[ii][jj];
        }
    }
}

// ---------------- agg1: h = relu(rs_in * seg_sum(y1[src]) + b1) ----------------
__global__ void agg1_kernel(const float* __restrict__ b1) {
    int d = blockIdx.x, t = threadIdx.x;   // 128 threads, 2 cols each
    int s = g_row_off[d], e = g_row_off[d + 1];
    float ax = 0.f, ay = 0.f;
    const float2* Y = (const float2*)g_y1;
    for (int i = s; i < e; i++) {
        int sn = g_perm_src[i];
        float2 v = Y[sn * (H1 / 2) + t];
        ax += v.x; ay += v.y;
    }
    float ri = g_rs_in[d];
    float h0 = fmaxf(ax * ri + b1[2 * t], 0.f);
    float h1 = fmaxf(ay * ri + b1[2 * t + 1], 0.f);
    ((float2*)g_h)[d * (H1 / 2) + t] = make_float2(h0, h1);
}

// ---------------- GEMM 23: y23 = (h * rs_out) @ [W2 | W3]   [M,256]x[256,256] ----------------
__global__ void gemm23_kernel(const float* __restrict__ W2, const float* __restrict__ W3, int M) {
    __shared__ float As[64][17];
    __shared__ float Bs[16][64];
    int tid = threadIdx.x, tx = tid & 15, ty = tid >> 4;
    int m0 = blockIdx.x * 64, n0 = blockIdx.y * 64;
    float acc[4][4] = {};
    for (int k0 = 0; k0 < H1; k0 += 16) {
#pragma unroll
        for (int q = 0; q < 4; q++) {
            int e = tid + q * 256;
            int r = e >> 4, c = e & 15;
            int row = m0 + r;
            As[r][c] = (row < M) ? g_h[row * H1 + k0 + c] * g_rs_out[row] : 0.f;
        }
#pragma unroll
        for (int q = 0; q < 4; q++) {
            int e = tid + q * 256;
            int r = e >> 6, c = e & 63;
            int col = n0 + c, kk = k0 + r;
            Bs[r][c] = (col < H2) ? W2[kk * H2 + col] : W3[kk * H2 + (col - H2)];
        }
        __syncthreads();
#pragma unroll
        for (int k = 0; k < 16; k++) {
            float a0 = As[ty * 4 + 0][k], a1 = As[ty * 4 + 1][k];
            float a2 = As[ty * 4 + 2][k], a3 = As[ty * 4 + 3][k];
            float4 b = *(const float4*)&Bs[k][tx * 4];
            acc[0][0] += a0 * b.x; acc[0][1] += a0 * b.y; acc[0][2] += a0 * b.z; acc[0][3] += a0 * b.w;
            acc[1][0] += a1 * b.x; acc[1][1] += a1 * b.y; acc[1][2] += a1 * b.z; acc[1][3] += a1 * b.w;
            acc[2][0] += a2 * b.x; acc[2][1] += a2 * b.y; acc[2][2] += a2 * b.z; acc[2][3] += a2 * b.w;
            acc[3][0] += a3 * b.x; acc[3][1] += a3 * b.y; acc[3][2] += a3 * b.z; acc[3][3] += a3 * b.w;
        }
        __syncthreads();
    }
#pragma unroll
    for (int ii = 0; ii < 4; ii++) {
        int row = m0 + ty * 4 + ii;
        if (row < M) {
#pragma unroll
            for (int jj = 0; jj < 4; jj++)
                g_y23[row * H1 + n0 + tx * 4 + jj] = acc[ii][jj];
        }
    }
}

// ---------------- aggz: s = rs_in*seg_sum(y23[src]); z = (s0+b2) + noise*exp(s1+b3) ----------------
__global__ void aggz_kernel(const float* __restrict__ b2, const float* __restrict__ b3,
                            const float* __restrict__ noise) {
    __shared__ float sm[H1];
    int d = blockIdx.x, t = threadIdx.x;   // 128 threads
    int s = g_row_off[d], e = g_row_off[d + 1];
    float ax = 0.f, ay = 0.f;
    const float2* Y = (const float2*)g_y23;
    for (int i = s; i < e; i++) {
        int sn = g_perm_src[i];
        float2 v = Y[sn * (H1 / 2) + t];
        ax += v.x; ay += v.y;
    }
    float ri = g_rs_in[d];
    sm[2 * t] = ax * ri;
    sm[2 * t + 1] = ay * ri;
    __syncthreads();
    if (t < 64) {
#pragma unroll
        for (int q = 0; q < 2; q++) {
            int c = 2 * t + q;
            float mean = sm[c] + b2[c];
            float ls = sm[c + H2] + b3[c];
            g_z[d * H2 + c] = mean + noise[d * H2 + c] * expf(ls);
        }
    }
}

// ---------------- final: out = sigmoid(z @ z^T), symmetric lower-tri tiles + mirror ----------------
__global__ void final_kernel(float* __restrict__ out, int n) {
    __shared__ float As[64][33];
    __shared__ float Bs[64][33];
    int p = blockIdx.x;
    int bi = (int)((sqrtf(8.0f * (float)p + 1.0f) - 1.0f) * 0.5f);
    while ((bi + 1) * (bi + 2) / 2 <= p) bi++;
    while (bi * (bi + 1) / 2 > p) bi--;
    int bj = p - bi * (bi + 1) / 2;        // bj <= bi
    int i0 = bi * 64, j0 = bj * 64;
    int tid = threadIdx.x, tx = tid & 15, ty = tid >> 4;
    float acc[4][4] = {};
    for (int k0 = 0; k0 < H2; k0 += 32) {
        __syncthreads();
#pragma unroll
        for (int q = 0; q < 8; q++) {
            int e = tid + q * 256;
            int r = e >> 5, c = e & 31;
            int ri = i0 + r;
            As[r][c] = (ri < n) ? g_z[ri * H2 + k0 + c] : 0.f;
            int rj = j0 + r;
            Bs[r][c] = (rj < n) ? g_z[rj * H2 + k0 + c] : 0.f;
        }
        __syncthreads();
#pragma unroll
        for (int k = 0; k < 32; k++) {
            float a0 = As[ty * 4 + 0][k], a1 = As[ty * 4 + 1][k];
            float a2 = As[ty * 4 + 2][k], a3 = As[ty * 4 + 3][k];
            float b0 = Bs[tx * 4 + 0][k], b1v = Bs[tx * 4 + 1][k];
            float b2v = Bs[tx * 4 + 2][k], b3v = Bs[tx * 4 + 3][k];
            acc[0][0] += a0 * b0; acc[0][1] += a0 * b1v; acc[0][2] += a0 * b2v; acc[0][3] += a0 * b3v;
            acc[1][0] += a1 * b0; acc[1][1] += a1 * b1v; acc[1][2] += a1 * b2v; acc[1][3] += a1 * b3v;
            acc[2][0] += a2 * b0; acc[2][1] += a2 * b1v; acc[2][2] += a2 * b2v; acc[2][3] += a2 * b3v;
            acc[3][0] += a3 * b0; acc[3][1] += a3 * b1v; acc[3][2] += a3 * b2v; acc[3][3] += a3 * b3v;
        }
    }
    // sigmoid
    float sig[4][4];
#pragma unroll
    for (int ii = 0; ii < 4; ii++)
#pragma unroll
        for (int jj = 0; jj < 4; jj++)
            sig[ii][jj] = 1.0f / (1.0f + __expf(-acc[ii][jj]));

    // direct store (i in tile bi, j in tile bj)
#pragma unroll
    for (int ii = 0; ii < 4; ii++) {
        int i = i0 + ty * 4 + ii;
        if (i < n) {
#pragma unroll
            for (int jj = 0; jj < 4; jj++) {
                int j = j0 + tx * 4 + jj;
                if (j < n) out[(size_t)i * n + j] = sig[ii][jj];
            }
        }
    }
    // mirror store (off-diagonal tiles): out[j][i] = out[i][j]
    if (bi != bj) {
#pragma unroll
        for (int jj = 0; jj < 4; jj++) {
            int j = j0 + tx * 4 + jj;
            if (j < n) {
#pragma unroll
                for (int ii = 0; ii < 4; ii++) {
                    int i = i0 + ty * 4 + ii;
                    if (i < n) out[(size_t)j * n + i] = sig[ii][jj];
                }
            }
        }
    }
}

// ---------------- launch ----------------
extern "C" void kernel_launch(void* const* d_in, const int* in_sizes, int n_in,
                              void* d_out, int out_size) {
    const float* features = (const float*)d_in[0];
    const int*   src      = (const int*)d_in[1];
    const int*   dst      = (const int*)d_in[2];
    const float* noise    = (const float*)d_in[3];
    const float* W1       = (const float*)d_in[4];
    const float* b1       = (const float*)d_in[5];
    const float* W2       = (const float*)d_in[6];
    const float* b2       = (const float*)d_in[7];
    const float* W3       = (const float*)d_in[8];
    const float* b3       = (const float*)d_in[9];
    int N = in_sizes[0] / IN_DIM;
    int E = in_sizes[1];
    float* out = (float*)d_out;

    zero_kernel<<<(N + 255) / 256, 256>>>(N);
    degree_kernel<<<(E + 255) / 256, 256>>>(src, dst, E);
    rs_kernel<<<(N + 255) / 256, 256>>>(N);
    scan_kernel<<<1, 1024>>>(N);
    perm_kernel<<<(E + 255) / 256, 256>>>(src, dst, E);

    dim3 g1((N + 63) / 64, H1 / 64);
    gemm1_kernel<<<g1, 256>>>(features, W1, N);
    agg1_kernel<<<N, 128>>>(b1);
    gemm23_kernel<<<g1, 256>>>(W2, W3, N);
    aggz_kernel<<<N, 128>>>(b2, b3, noise);

    int T = (N + 63) / 64;
    final_kernel<<<T * (T + 1) / 2, 256>>>(out, N);
}

// round 3
// speedup vs baseline: 1.3492x; 1.3492x over previous
#include <cuda_runtime.h>

#define MAXN 10000
#define MAXE 320000
#define IN_DIM 512
#define H1 256
#define H2 128

// ---------------- scratch (device globals; no allocation allowed) ----------------
__device__ int   g_deg_out[MAXN];
__device__ int   g_deg_in[MAXN];
__device__ int   g_cnt[MAXN];
__device__ float g_rs_out[MAXN];
__device__ float g_rs_in[MAXN];
__device__ int   g_row_off[MAXN + 1];
__device__ int   g_perm_src[MAXE];
__device__ float g_y1[MAXN * H1];    // (x*rs_out) @ W1
__device__ float g_h[MAXN * H1];     // relu(conv1)
__device__ float g_y23[MAXN * H1];   // (h*rs_out) @ [W2|W3]
__device__ float g_z[MAXN * H2];     // mean + noise*exp(log_std)

// ---------------- packed f32x2 helpers ----------------
__device__ __forceinline__ unsigned long long pack_dup(float a) {
    unsigned long long r;
    unsigned int ai = __float_as_uint(a);
    asm("mov.b64 %0, {%1, %1};" : "=l"(r) : "r"(ai));
    return r;
}
__device__ __forceinline__ unsigned long long pack2(float x, float y) {
    unsigned long long r;
    asm("mov.b64 %0, {%1, %2};" : "=l"(r) : "r"(__float_as_uint(x)), "r"(__float_as_uint(y)));
    return r;
}
__device__ __forceinline__ void ffma2(unsigned long long& d, unsigned long long a, unsigned long long b) {
    asm("fma.rn.f32x2 %0, %1, %2, %3;" : "=l"(d) : "l"(a), "l"(b), "l"(d));
}
__device__ __forceinline__ float2 unpack2(unsigned long long v) {
    unsigned int lo, hi;
    asm("mov.b64 {%0, %1}, %2;" : "=r"(lo), "=r"(hi) : "l"(v));
    return make_float2(__uint_as_float(lo), __uint_as_float(hi));
}
__device__ __forceinline__ float sigm(float x) {
    return 1.0f / (1.0f + __expf(-x));
}

// ---------------- small setup kernels ----------------
__global__ void zero_kernel(int n) {
    int i = blockIdx.x * blockDim.x + threadIdx.x;
    if (i < n) { g_deg_out[i] = 0; g_deg_in[i] = 0; g_cnt[i] = 0; }
}

__global__ void degree_kernel(const int* __restrict__ src, const int* __restrict__ dst, int e) {
    int i = blockIdx.x * blockDim.x + threadIdx.x;
    if (i < e) {
        atomicAdd(&g_deg_out[src[i]], 1);
        atomicAdd(&g_deg_in[dst[i]], 1);
    }
}

__global__ void rs_kernel(int n) {
    int i = blockIdx.x * blockDim.x + threadIdx.x;
    if (i < n) {
        g_rs_out[i] = rsqrtf(fmaxf((float)g_deg_out[i], 1.0f));
        g_rs_in[i]  = rsqrtf(fmaxf((float)g_deg_in[i], 1.0f));
    }
}

// single-block warp-shuffle exclusive scan of deg_in -> row_off
__global__ void scan_kernel(int n) {
    __shared__ int wsum[32];
    int t = threadIdx.x, lane = t & 31, w = t >> 5;
    int carry = 0;
    for (int base = 0; base < n; base += 1024) {
        int v = (base + t < n) ? g_deg_in[base + t] : 0;
        int s = v;
#pragma unroll
        for (int off = 1; off < 32; off <<= 1) {
            int u = __shfl_up_sync(0xffffffffu, s, off);
            if (lane >= off) s += u;
        }
        __syncthreads();                     // protect wsum from previous iter reads
        if (lane == 31) wsum[w] = s;
        __syncthreads();
        if (w == 0) {
            int x = wsum[lane];
#pragma unroll
            for (int off = 1; off < 32; off <<= 1) {
                int u = __shfl_up_sync(0xffffffffu, x, off);
                if (lane >= off) x += u;
            }
            wsum[lane] = x;
        }
        __syncthreads();
        int woff = (w > 0) ? wsum[w - 1] : 0;
        if (base + t < n) g_row_off[base + t] = carry + woff + s - v;
        carry += wsum[31];
    }
    if (t == 0) g_row_off[n] = carry;
}

__global__ void perm_kernel(const int* __restrict__ src, const int* __restrict__ dst, int e) {
    int i = blockIdx.x * blockDim.x + threadIdx.x;
    if (i < e) {
        int d = dst[i];
        int pos = atomicAdd(&g_cnt[d], 1);
        g_perm_src[g_row_off[d] + pos] = src[i];
    }
}

// ---------------- GEMM 1: y1 = (X * rs_out) @ W1   [M,512]x[512,256] ----------------
__global__ void gemm1_kernel(const float* __restrict__ X, const float* __restrict__ W, int M) {
    __shared__ float As[64][17];
    __shared__ float Bs[16][64];
    int tid = threadIdx.x, tx = tid & 15, ty = tid >> 4;
    int m0 = blockIdx.x * 64, n0 = blockIdx.y * 64;
    unsigned long long acc[4][2] = {};
    for (int k0 = 0; k0 < IN_DIM; k0 += 16) {
#pragma unroll
        for (int q = 0; q < 4; q++) {
            int e = tid + q * 256;
            int r = e >> 4, c = e & 15;
            int row = m0 + r;
            As[r][c] = (row < M) ? X[row * IN_DIM + k0 + c] * g_rs_out[row] : 0.f;
        }
#pragma unroll
        for (int q = 0; q < 4; q++) {
            int e = tid + q * 256;
            int r = e >> 6, c = e & 63;
            Bs[r][c] = W[(k0 + r) * H1 + n0 + c];
        }
        __syncthreads();
#pragma unroll
        for (int k = 0; k < 16; k++) {
            float4 b = *(const float4*)&Bs[k][tx * 4];
            unsigned long long b01 = pack2(b.x, b.y), b23 = pack2(b.z, b.w);
#pragma unroll
            for (int ii = 0; ii < 4; ii++) {
                unsigned long long a = pack_dup(As[ty * 4 + ii][k]);
                ffma2(acc[ii][0], a, b01);
                ffma2(acc[ii][1], a, b23);
            }
        }
        __syncthreads();
    }
#pragma unroll
    for (int ii = 0; ii < 4; ii++) {
        int row = m0 + ty * 4 + ii;
        if (row < M) {
            float2 v0 = unpack2(acc[ii][0]);
            float2 v1 = unpack2(acc[ii][1]);
            *(float2*)&g_y1[row * H1 + n0 + tx * 4]     = v0;
            *(float2*)&g_y1[row * H1 + n0 + tx * 4 + 2] = v1;
        }
    }
}

// ---------------- agg1: h = relu(rs_in * seg_sum(y1[src]) + b1) ----------------
__global__ void agg1_kernel(const float* __restrict__ b1) {
    int d = blockIdx.x, t = threadIdx.x;   // 128 threads, 2 cols each
    int s = g_row_off[d], e = g_row_off[d + 1];
    float ax = 0.f, ay = 0.f;
    const float2* Y = (const float2*)g_y1;
    for (int i = s; i < e; i++) {
        int sn = g_perm_src[i];
        float2 v = Y[sn * (H1 / 2) + t];
        ax += v.x; ay += v.y;
    }
    float ri = g_rs_in[d];
    float h0 = fmaxf(ax * ri + b1[2 * t], 0.f);
    float h1 = fmaxf(ay * ri + b1[2 * t + 1], 0.f);
    ((float2*)g_h)[d * (H1 / 2) + t] = make_float2(h0, h1);
}

// ---------------- GEMM 23: y23 = (h * rs_out) @ [W2 | W3]   [M,256]x[256,256] ----------------
__global__ void gemm23_kernel(const float* __restrict__ W2, const float* __restrict__ W3, int M) {
    __shared__ float As[64][17];
    __shared__ float Bs[16][64];
    int tid = threadIdx.x, tx = tid & 15, ty = tid >> 4;
    int m0 = blockIdx.x * 64, n0 = blockIdx.y * 64;
    unsigned long long acc[4][2] = {};
    for (int k0 = 0; k0 < H1; k0 += 16) {
#pragma unroll
        for (int q = 0; q < 4; q++) {
            int e = tid + q * 256;
            int r = e >> 4, c = e & 15;
            int row = m0 + r;
            As[r][c] = (row < M) ? g_h[row * H1 + k0 + c] * g_rs_out[row] : 0.f;
        }
#pragma unroll
        for (int q = 0; q < 4; q++) {
            int e = tid + q * 256;
            int r = e >> 6, c = e & 63;
            int col = n0 + c, kk = k0 + r;
            Bs[r][c] = (col < H2) ? W2[kk * H2 + col] : W3[kk * H2 + (col - H2)];
        }
        __syncthreads();
#pragma unroll
        for (int k = 0; k < 16; k++) {
            float4 b = *(const float4*)&Bs[k][tx * 4];
            unsigned long long b01 = pack2(b.x, b.y), b23 = pack2(b.z, b.w);
#pragma unroll
            for (int ii = 0; ii < 4; ii++) {
                unsigned long long a = pack_dup(As[ty * 4 + ii][k]);
                ffma2(acc[ii][0], a, b01);
                ffma2(acc[ii][1], a, b23);
            }
        }
        __syncthreads();
    }
#pragma unroll
    for (int ii = 0; ii < 4; ii++) {
        int row = m0 + ty * 4 + ii;
        if (row < M) {
            float2 v0 = unpack2(acc[ii][0]);
            float2 v1 = unpack2(acc[ii][1]);
            *(float2*)&g_y23[row * H1 + n0 + tx * 4]     = v0;
            *(float2*)&g_y23[row * H1 + n0 + tx * 4 + 2] = v1;
        }
    }
}

// ---------------- aggz: s = rs_in*seg_sum(y23[src]); z = (s0+b2) + noise*exp(s1+b3) ----------------
__global__ void aggz_kernel(const float* __restrict__ b2, const float* __restrict__ b3,
                            const float* __restrict__ noise) {
    __shared__ float sm[H1];
    int d = blockIdx.x, t = threadIdx.x;   // 128 threads
    int s = g_row_off[d], e = g_row_off[d + 1];
    float ax = 0.f, ay = 0.f;
    const float2* Y = (const float2*)g_y23;
    for (int i = s; i < e; i++) {
        int sn = g_perm_src[i];
        float2 v = Y[sn * (H1 / 2) + t];
        ax += v.x; ay += v.y;
    }
    float ri = g_rs_in[d];
    sm[2 * t] = ax * ri;
    sm[2 * t + 1] = ay * ri;
    __syncthreads();
    if (t < 64) {
#pragma unroll
        for (int q = 0; q < 2; q++) {
            int c = 2 * t + q;
            float mean = sm[c] + b2[c];
            float ls = sm[c + H2] + b3[c];
            g_z[d * H2 + c] = mean + noise[d * H2 + c] * expf(ls);
        }
    }
}

// ---------------- final: out = sigmoid(z @ z^T), 128x128 tiles, f32x2 FMA ----------------
// Lower-triangular tile pairs + mirror store of the transpose.
__global__ void __launch_bounds__(256) final_kernel(float* __restrict__ out, int n) {
    __shared__ float As[32][132];   // [k][row], 16B-aligned rows for float4 LDS
    __shared__ float Bs[32][132];

    int p = blockIdx.x;
    int bi = (int)((sqrtf(8.0f * (float)p + 1.0f) - 1.0f) * 0.5f);
    while ((bi + 1) * (bi + 2) / 2 <= p) bi++;
    while (bi * (bi + 1) / 2 > p) bi--;
    int bj = p - bi * (bi + 1) / 2;        // bj <= bi
    int i0 = bi * 128, j0 = bj * 128;

    int tid = threadIdx.x, tx = tid & 15, ty = tid >> 4;
    unsigned long long acc[8][4] = {};

    for (int k0 = 0; k0 < H2; k0 += 32) {
        __syncthreads();
#pragma unroll
        for (int q = 0; q < 4; q++) {
            int idx = q * 256 + tid;      // 1024 float4s cover 128 rows x 32 k
            int row = idx >> 3;
            int kc  = (idx & 7) * 4;
            float4 va = make_float4(0.f, 0.f, 0.f, 0.f);
            float4 vb = make_float4(0.f, 0.f, 0.f, 0.f);
            int gi = i0 + row;
            int gj = j0 + row;
            if (gi < n) va = *(const float4*)&g_z[gi * H2 + k0 + kc];
            if (gj < n) vb = *(const float4*)&g_z[gj * H2 + k0 + kc];
            As[kc + 0][row] = va.x; As[kc + 1][row] = va.y;
            As[kc + 2][row] = va.z; As[kc + 3][row] = va.w;
            Bs[kc + 0][row] = vb.x; Bs[kc + 1][row] = vb.y;
            Bs[kc + 2][row] = vb.z; Bs[kc + 3][row] = vb.w;
        }
        __syncthreads();
#pragma unroll 4
        for (int k = 0; k < 32; k++) {
            float4 al = *(const float4*)&As[k][ty * 4];
            float4 ah = *(const float4*)&As[k][64 + ty * 4];
            float4 bl = *(const float4*)&Bs[k][tx * 4];
            float4 bh = *(const float4*)&Bs[k][64 + tx * 4];
            unsigned long long b0 = pack2(bl.x, bl.y), b1 = pack2(bl.z, bl.w);
            unsigned long long b2 = pack2(bh.x, bh.y), b3 = pack2(bh.z, bh.w);
            float av[8] = {al.x, al.y, al.z, al.w, ah.x, ah.y, ah.z, ah.w};
#pragma unroll
            for (int r = 0; r < 8; r++) {
                unsigned long long a = pack_dup(av[r]);
                ffma2(acc[r][0], a, b0);
                ffma2(acc[r][1], a, b1);
                ffma2(acc[r][2], a, b2);
                ffma2(acc[r][3], a, b3);
            }
        }
    }

    // sigmoid (in float2 form; acc dead after this)
    float2 sg[8][4];
#pragma unroll
    for (int r = 0; r < 8; r++)
#pragma unroll
        for (int q = 0; q < 4; q++) {
            float2 v = unpack2(acc[r][q]);
            sg[r][q] = make_float2(sigm(v.x), sigm(v.y));
        }

    bool n2ok = ((n & 1) == 0);
    bool n4ok = ((n & 3) == 0);

    // direct store: out[i][j]
#pragma unroll
    for (int r = 0; r < 8; r++) {
        int i = i0 + ((r < 4) ? (ty * 4 + r) : (64 + ty * 4 + r - 4));
        if (i < n) {
#pragma unroll
            for (int q = 0; q < 4; q++) {
                int j = j0 + ((q < 2) ? (tx * 4 + 2 * q) : (64 + tx * 4 + 2 * (q - 2)));
                size_t off = (size_t)i * n + j;
                if (j + 1 < n && n2ok) {
                    *(float2*)&out[off] = sg[r][q];
                } else {
                    if (j < n)     out[off]     = sg[r][q].x;
                    if (j + 1 < n) out[off + 1] = sg[r][q].y;
                }
            }
        }
    }

    // mirror store: out[j][i] (transpose), rows of the mirror are contiguous in i
    if (bi != bj) {
#pragma unroll
        for (int q = 0; q < 4; q++) {
#pragma unroll
            for (int h = 0; h < 2; h++) {
                int j = j0 + ((q < 2) ? (tx * 4 + 2 * q) : (64 + tx * 4 + 2 * (q - 2))) + h;
                if (j >= n) continue;
                // low 4 rows
                {
                    int iv = i0 + ty * 4;
                    float4 v = h ? make_float4(sg[0][q].y, sg[1][q].y, sg[2][q].y, sg[3][q].y)
                                 : make_float4(sg[0][q].x, sg[1][q].x, sg[2][q].x, sg[3][q].x);
                    size_t off = (size_t)j * n + iv;
                    if (iv + 3 < n && n4ok) {
                        *(float4*)&out[off] = v;
                    } else {
                        float a[4] = {v.x, v.y, v.z, v.w};
                        for (int t2 = 0; t2 < 4; t2++)
                            if (iv + t2 < n) out[off + t2] = a[t2];
                    }
                }
                // high 4 rows
                {
                    int iv = i0 + 64 + ty * 4;
                    float4 v = h ? make_float4(sg[4][q].y, sg[5][q].y, sg[6][q].y, sg[7][q].y)
                                 : make_float4(sg[4][q].x, sg[5][q].x, sg[6][q].x, sg[7][q].x);
                    size_t off = (size_t)j * n + iv;
                    if (iv + 3 < n && n4ok) {
                        *(float4*)&out[off] = v;
                    } else {
                        float a[4] = {v.x, v.y, v.z, v.w};
                        for (int t2 = 0; t2 < 4; t2++)
                            if (iv + t2 < n) out[off + t2] = a[t2];
                    }
                }
            }
        }
    }
}

// ---------------- launch ----------------
extern "C" void kernel_launch(void* const* d_in, const int* in_sizes, int n_in,
                              void* d_out, int out_size) {
    const float* features = (const float*)d_in[0];
    const int*   src      = (const int*)d_in[1];
    const int*   dst      = (const int*)d_in[2];
    const float* noise    = (const float*)d_in[3];
    const float* W1       = (const float*)d_in[4];
    const float* b1       = (const float*)d_in[5];
    const float* W2       = (const float*)d_in[6];
    const float* b2       = (const float*)d_in[7];
    const float* W3       = (const float*)d_in[8];
    const float* b3       = (const float*)d_in[9];
    int N = in_sizes[0] / IN_DIM;
    int E = in_sizes[1];
    float* out = (float*)d_out;

    zero_kernel<<<(N + 255) / 256, 256>>>(N);
    degree_kernel<<<(E + 255) / 256, 256>>>(src, dst, E);
    rs_kernel<<<(N + 255) / 256, 256>>>(N);
    scan_kernel<<<1, 1024>>>(N);
    perm_kernel<<<(E + 255) / 256, 256>>>(src, dst, E);

    dim3 g1((N + 63) / 64, H1 / 64);
    gemm1_kernel<<<g1, 256>>>(features, W1, N);
    agg1_kernel<<<N, 128>>>(b1);
    gemm23_kernel<<<g1, 256>>>(W2, W3, N);
    aggz_kernel<<<N, 128>>>(b2, b3, noise);

    int T = (N + 127) / 128;
    final_kernel<<<T * (T + 1) / 2, 256>>>(out, N);
}

// round 6
// speedup vs baseline: 1.4958x; 1.1087x over previous
#include <cuda_runtime.h>
#include <cuda_bf16.h>
#include <cstdint>

#define MAXN 10000
#define MAXE 320000
#define IN_DIM 512
#define H1 256
#define H2 128

// ---------------- scratch (device globals; no allocation allowed) ----------------
__device__ int   g_deg_out[MAXN];
__device__ int   g_deg_in[MAXN];
__device__ int   g_cnt[MAXN];
__device__ float g_rs_out[MAXN];
__device__ float g_rs_in[MAXN];
__device__ int   g_row_off[MAXN + 1];
__device__ int   g_perm_src[MAXE];
__device__ float g_y1[MAXN * H1];    // (x*rs_out) @ W1
__device__ float g_h[MAXN * H1];     // relu(conv1)
__device__ float g_y23[MAXN * H1];   // (h*rs_out) @ [W2|W3]
__device__ __align__(16) __nv_bfloat16 g_zhi[MAXN * H2];
__device__ __align__(16) __nv_bfloat16 g_zlo[MAXN * H2];

// ---------------- packed f32x2 helpers ----------------
__device__ __forceinline__ unsigned long long pack_dup(float a) {
    unsigned long long r;
    unsigned int ai = __float_as_uint(a);
    asm("mov.b64 %0, {%1, %1};" : "=l"(r) : "r"(ai));
    return r;
}
__device__ __forceinline__ unsigned long long pack2(float x, float y) {
    unsigned long long r;
    asm("mov.b64 %0, {%1, %2};" : "=l"(r) : "r"(__float_as_uint(x)), "r"(__float_as_uint(y)));
    return r;
}
__device__ __forceinline__ void ffma2(unsigned long long& d, unsigned long long a, unsigned long long b) {
    asm("fma.rn.f32x2 %0, %1, %2, %3;" : "=l"(d) : "l"(a), "l"(b), "l"(d));
}
__device__ __forceinline__ float2 unpack2(unsigned long long v) {
    unsigned int lo, hi;
    asm("mov.b64 {%0, %1}, %2;" : "=r"(lo), "=r"(hi) : "l"(v));
    return make_float2(__uint_as_float(lo), __uint_as_float(hi));
}
__device__ __forceinline__ float sigm(float x) {
    return 1.0f / (1.0f + __expf(-x));
}

// ---------------- mma.sync helpers (arch-neutral PTX, works on plain sm_103) ----------------
__device__ __forceinline__ uint32_t smem_u32(const void* p) {
    uint32_t a;
    asm("{ .reg .u64 t; cvta.to.shared.u64 t, %1; cvt.u32.u64 %0, t; }" : "=r"(a) : "l"(p));
    return a;
}
__device__ __forceinline__ void ldsm_x4(uint32_t a[4], uint32_t addr) {
    asm volatile("ldmatrix.sync.aligned.m8n8.x4.shared.b16 {%0,%1,%2,%3}, [%4];"
        : "=r"(a[0]), "=r"(a[1]), "=r"(a[2]), "=r"(a[3]) : "r"(addr));
}
__device__ __forceinline__ void ldsm_x2(uint32_t b[2], uint32_t addr) {
    asm volatile("ldmatrix.sync.aligned.m8n8.x2.shared.b16 {%0,%1}, [%2];"
        : "=r"(b[0]), "=r"(b[1]) : "r"(addr));
}
__device__ __forceinline__ void mma_bf16(float d[4], const uint32_t a[4], const uint32_t b[2]) {
    asm volatile("mma.sync.aligned.m16n8k16.row.col.f32.bf16.bf16.f32 "
        "{%0,%1,%2,%3}, {%4,%5,%6,%7}, {%8,%9}, {%0,%1,%2,%3};"
        : "+f"(d[0]), "+f"(d[1]), "+f"(d[2]), "+f"(d[3])
        : "r"(a[0]), "r"(a[1]), "r"(a[2]), "r"(a[3]), "r"(b[0]), "r"(b[1]));
}

// ---------------- small setup kernels ----------------
__global__ void zero_kernel(int n) {
    int i = blockIdx.x * blockDim.x + threadIdx.x;
    if (i < n) { g_deg_out[i] = 0; g_deg_in[i] = 0; g_cnt[i] = 0; }
}

__global__ void degree_kernel(const int* __restrict__ src, const int* __restrict__ dst, int e) {
    int i = blockIdx.x * blockDim.x + threadIdx.x;
    if (i < e) {
        atomicAdd(&g_deg_out[src[i]], 1);
        atomicAdd(&g_deg_in[dst[i]], 1);
    }
}

__global__ void rs_kernel(int n) {
    int i = blockIdx.x * blockDim.x + threadIdx.x;
    if (i < n) {
        g_rs_out[i] = rsqrtf(fmaxf((float)g_deg_out[i], 1.0f));
        g_rs_in[i]  = rsqrtf(fmaxf((float)g_deg_in[i], 1.0f));
    }
}

// single-block single-pass scan: each thread serially scans its chunk, block-scan of totals
__global__ void scan_kernel(int n) {
    __shared__ int wsum[32];
    int t = threadIdx.x, lane = t & 31, w = t >> 5;
    int chunk = (n + 1023) >> 10;
    int s0 = t * chunk;
    int local[16];   // chunk <= 16 assumed for n <= 16384
    int tot = 0;
#pragma unroll
    for (int q = 0; q < 16; q++) {
        if (q < chunk) {
            int idx = s0 + q;
            int v = (idx < n) ? g_deg_in[idx] : 0;
            local[q] = tot;
            tot += v;
        }
    }
    int s = tot;
#pragma unroll
    for (int off = 1; off < 32; off <<= 1) {
        int u = __shfl_up_sync(0xffffffffu, s, off);
        if (lane >= off) s += u;
    }
    if (lane == 31) wsum[w] = s;
    __syncthreads();
    if (w == 0) {
        int x = wsum[lane];
#pragma unroll
        for (int off = 1; off < 32; off <<= 1) {
            int u = __shfl_up_sync(0xffffffffu, x, off);
            if (lane >= off) x += u;
        }
        wsum[lane] = x;
    }
    __syncthreads();
    int base = s - tot + ((w > 0) ? wsum[w - 1] : 0);
#pragma unroll
    for (int q = 0; q < 16; q++) {
        if (q < chunk) {
            int idx = s0 + q;
            if (idx < n) g_row_off[idx] = base + local[q];
        }
    }
    if (t == 1023) g_row_off[n] = base + tot;
}

__global__ void perm_kernel(const int* __restrict__ src, const int* __restrict__ dst, int e) {
    int i = blockIdx.x * blockDim.x + threadIdx.x;
    if (i < e) {
        int d = dst[i];
        int pos = atomicAdd(&g_cnt[d], 1);
        g_perm_src[g_row_off[d] + pos] = src[i];
    }
}

// ---------------- GEMM 1: y1 = (X * rs_out) @ W1   [M,512]x[512,256] ----------------
__global__ void gemm1_kernel(const float* __restrict__ X, const float* __restrict__ W, int M) {
    __shared__ float As[64][17];
    __shared__ float Bs[16][64];
    int tid = threadIdx.x, tx = tid & 15, ty = tid >> 4;
    int m0 = blockIdx.x * 64, n0 = blockIdx.y * 64;
    unsigned long long acc[4][2] = {};
    for (int k0 = 0; k0 < IN_DIM; k0 += 16) {
#pragma unroll
        for (int q = 0; q < 4; q++) {
            int e = tid + q * 256;
            int r = e >> 4, c = e & 15;
            int row = m0 + r;
            As[r][c] = (row < M) ? X[row * IN_DIM + k0 + c] * g_rs_out[row] : 0.f;
        }
#pragma unroll
        for (int q = 0; q < 4; q++) {
            int e = tid + q * 256;
            int r = e >> 6, c = e & 63;
            Bs[r][c] = W[(k0 + r) * H1 + n0 + c];
        }
        __syncthreads();
#pragma unroll
        for (int k = 0; k < 16; k++) {
            float4 b = *(const float4*)&Bs[k][tx * 4];
            unsigned long long b01 = pack2(b.x, b.y), b23 = pack2(b.z, b.w);
#pragma unroll
            for (int ii = 0; ii < 4; ii++) {
                unsigned long long a = pack_dup(As[ty * 4 + ii][k]);
                ffma2(acc[ii][0], a, b01);
                ffma2(acc[ii][1], a, b23);
            }
        }
        __syncthreads();
    }
#pragma unroll
    for (int ii = 0; ii < 4; ii++) {
        int row = m0 + ty * 4 + ii;
        if (row < M) {
            float2 v0 = unpack2(acc[ii][0]);
            float2 v1 = unpack2(acc[ii][1]);
            *(float2*)&g_y1[row * H1 + n0 + tx * 4]     = v0;
            *(float2*)&g_y1[row * H1 + n0 + tx * 4 + 2] = v1;
        }
    }
}

// ---------------- agg1: h = relu(rs_in * seg_sum(y1[src]) + b1) ----------------
__global__ void agg1_kernel(const float* __restrict__ b1) {
    int d = blockIdx.x, t = threadIdx.x;
    int s = g_row_off[d], e = g_row_off[d + 1];
    float ax = 0.f, ay = 0.f;
    const float2* Y = (const float2*)g_y1;
    for (int i = s; i < e; i++) {
        int sn = g_perm_src[i];
        float2 v = Y[sn * (H1 / 2) + t];
        ax += v.x; ay += v.y;
    }
    float ri = g_rs_in[d];
    float h0 = fmaxf(ax * ri + b1[2 * t], 0.f);
    float h1 = fmaxf(ay * ri + b1[2 * t + 1], 0.f);
    ((float2*)g_h)[d * (H1 / 2) + t] = make_float2(h0, h1);
}

// ---------------- GEMM 23: y23 = (h * rs_out) @ [W2 | W3]   [M,256]x[256,256] ----------------
__global__ void gemm23_kernel(const float* __restrict__ W2, const float* __restrict__ W3, int M) {
    __shared__ float As[64][17];
    __shared__ float Bs[16][64];
    int tid = threadIdx.x, tx = tid & 15, ty = tid >> 4;
    int m0 = blockIdx.x * 64, n0 = blockIdx.y * 64;
    unsigned long long acc[4][2] = {};
    for (int k0 = 0; k0 < H1; k0 += 16) {
#pragma unroll
        for (int q = 0; q < 4; q++) {
            int e = tid + q * 256;
            int r = e >> 4, c = e & 15;
            int row = m0 + r;
            As[r][c] = (row < M) ? g_h[row * H1 + k0 + c] * g_rs_out[row] : 0.f;
        }
#pragma unroll
        for (int q = 0; q < 4; q++) {
            int e = tid + q * 256;
            int r = e >> 6, c = e & 63;
            int col = n0 + c, kk = k0 + r;
            Bs[r][c] = (col < H2) ? W2[kk * H2 + col] : W3[kk * H2 + (col - H2)];
        }
        __syncthreads();
#pragma unroll
        for (int k = 0; k < 16; k++) {
            float4 b = *(const float4*)&Bs[k][tx * 4];
            unsigned long long b01 = pack2(b.x, b.y), b23 = pack2(b.z, b.w);
#pragma unroll
            for (int ii = 0; ii < 4; ii++) {
                unsigned long long a = pack_dup(As[ty * 4 + ii][k]);
                ffma2(acc[ii][0], a, b01);
                ffma2(acc[ii][1], a, b23);
            }
        }
        __syncthreads();
    }
#pragma unroll
    for (int ii = 0; ii < 4; ii++) {
        int row = m0 + ty * 4 + ii;
        if (row < M) {
            float2 v0 = unpack2(acc[ii][0]);
            float2 v1 = unpack2(acc[ii][1]);
            *(float2*)&g_y23[row * H1 + n0 + tx * 4]     = v0;
            *(float2*)&g_y23[row * H1 + n0 + tx * 4 + 2] = v1;
        }
    }
}

// ---------------- aggz: z = (s0+b2) + noise*exp(s1+b3); emit bf16 hi/lo split ----------------
__global__ void aggz_kernel(const float* __restrict__ b2, const float* __restrict__ b3,
                            const float* __restrict__ noise) {
    __shared__ float sm[H1];
    int d = blockIdx.x, t = threadIdx.x;
    int s = g_row_off[d], e = g_row_off[d + 1];
    float ax = 0.f, ay = 0.f;
    const float2* Y = (const float2*)g_y23;
    for (int i = s; i < e; i++) {
        int sn = g_perm_src[i];
        float2 v = Y[sn * (H1 / 2) + t];
        ax += v.x; ay += v.y;
    }
    float ri = g_rs_in[d];
    sm[2 * t] = ax * ri;
    sm[2 * t + 1] = ay * ri;
    __syncthreads();
    if (t < 64) {
#pragma unroll
        for (int q = 0; q < 2; q++) {
            int c = 2 * t + q;
            float mean = sm[c] + b2[c];
            float ls = sm[c + H2] + b3[c];
            float zv = mean + noise[d * H2 + c] * expf(ls);
            __nv_bfloat16 hi = __float2bfloat16(zv);
            float hif = __bfloat162float(hi);
            __nv_bfloat16 lo = __float2bfloat16(zv - hif);
            g_zhi[d * H2 + c] = hi;
            g_zlo[d * H2 + c] = lo;
        }
    }
}

// ---------------- final decoder: mma.sync bf16 hi/lo, 128x128 tiles ----------------
// smem: 4 bf16 buffers [128 rows x 272B (128 bf16 + 8 pad)]
#define ROWB 272
#define BUF_SZ (128 * ROWB)              // 34816
#define SM_HI_I 0
#define SM_LO_I (BUF_SZ)
#define SM_HI_J (2 * BUF_SZ)
#define SM_LO_J (3 * BUF_SZ)
#define SM_TOTAL (4 * BUF_SZ)            // 139264; transpose staging (67584B) aliases offset 0

__global__ void __launch_bounds__(256) final_kernel(float* __restrict__ out, int n) {
    extern __shared__ char smem_raw[];
    int tid = threadIdx.x;
    int w = tid >> 5, lane = tid & 31;

    int p = blockIdx.x;
    int bi = (int)((sqrtf(8.0f * (float)p + 1.0f) - 1.0f) * 0.5f);
    while ((bi + 1) * (bi + 2) / 2 <= p) bi++;
    while (bi * (bi + 1) / 2 > p) bi--;
    int bj = p - bi * (bi + 1) / 2;        // bj <= bi
    int i0 = bi * 128, j0 = bj * 128;

    // ---- load tiles (hi/lo for i-rows and j-rows), zero-fill OOB rows ----
    const uint4 zz = make_uint4(0u, 0u, 0u, 0u);
    for (int c = tid; c < 2048; c += 256) {
        int row = c >> 4, seg = c & 15;
        int off = row * ROWB + seg * 16;
        int gi = i0 + row, gj = j0 + row;
        uint4 hi_i = zz, lo_i = zz, hi_j = zz, lo_j = zz;
        if (gi < n) {
            hi_i = *(const uint4*)&g_zhi[gi * H2 + seg * 8];
            lo_i = *(const uint4*)&g_zlo[gi * H2 + seg * 8];
        }
        if (gj < n) {
            hi_j = *(const uint4*)&g_zhi[gj * H2 + seg * 8];
            lo_j = *(const uint4*)&g_zlo[gj * H2 + seg * 8];
        }
        *(uint4*)(smem_raw + SM_HI_I + off) = hi_i;
        *(uint4*)(smem_raw + SM_LO_I + off) = lo_i;
        *(uint4*)(smem_raw + SM_HI_J + off) = hi_j;
        *(uint4*)(smem_raw + SM_LO_J + off) = lo_j;
    }
    __syncthreads();

    uint32_t smb = smem_u32(smem_raw);
    int warp_m = w & 1, warp_n = w >> 1;       // 2 x 4 warp grid; warp tile 64m x 32n

    // lane-dependent ldmatrix base offsets
    // A (x4): lanes 0-7:m0-7/k0, 8-15:m8-15/k0, 16-23:m0-7/k8, 24-31:m8-15/k8
    uint32_t aoffA = (uint32_t)((warp_m * 64 + (lane & 15)) * ROWB + (lane >> 4) * 16);
    // B (x2): lanes 0-7: n0-7/k0, 8-15: n0-7/k8
    uint32_t aoffB = (uint32_t)((warp_n * 32 + (lane & 7)) * ROWB + ((lane >> 3) & 1) * 16);

    float acc[4][4][4] = {};   // [mfrag][nfrag][reg]

    for (int ks = 0; ks < 8; ks++) {
        uint32_t k2 = (uint32_t)(ks * 32);   // 16 bf16 = 32 bytes per k-step
        uint32_t Ahi[4][4], Bhi[4][2], Blo[4][2];
#pragma unroll
        for (int mf = 0; mf < 4; mf++)
            ldsm_x4(Ahi[mf], smb + SM_HI_I + aoffA + mf * (16 * ROWB) + k2);
#pragma unroll
        for (int nf = 0; nf < 4; nf++) {
            ldsm_x2(Bhi[nf], smb + SM_HI_J + aoffB + nf * (8 * ROWB) + k2);
            ldsm_x2(Blo[nf], smb + SM_LO_J + aoffB + nf * (8 * ROWB) + k2);
        }
#pragma unroll
        for (int mf = 0; mf < 4; mf++)
#pragma unroll
            for (int nf = 0; nf < 4; nf++) {
                mma_bf16(acc[mf][nf], Ahi[mf], Bhi[nf]);
                mma_bf16(acc[mf][nf], Ahi[mf], Blo[nf]);
            }
        uint32_t Alo[4][4];
#pragma unroll
        for (int mf = 0; mf < 4; mf++)
            ldsm_x4(Alo[mf], smb + SM_LO_I + aoffA + mf * (16 * ROWB) + k2);
#pragma unroll
        for (int mf = 0; mf < 4; mf++)
#pragma unroll
            for (int nf = 0; nf < 4; nf++)
                mma_bf16(acc[mf][nf], Alo[mf], Bhi[nf]);
    }

    // ---- sigmoid in-place ----
#pragma unroll
    for (int mf = 0; mf < 4; mf++)
#pragma unroll
        for (int nf = 0; nf < 4; nf++)
#pragma unroll
            for (int r = 0; r < 4; r++)
                acc[mf][nf][r] = sigm(acc[mf][nf][r]);

    int g = lane >> 2, q = lane & 3;

    // ---- direct store: out[i][j] (32B sectors, coalesced within quads) ----
#pragma unroll
    for (int mf = 0; mf < 4; mf++) {
#pragma unroll
        for (int rr = 0; rr < 2; rr++) {
            int i = i0 + warp_m * 64 + mf * 16 + g + rr * 8;
            if (i < n) {
#pragma unroll
                for (int nf = 0; nf < 4; nf++) {
                    int j = j0 + warp_n * 32 + nf * 8 + q * 2;
                    if (j + 1 < n) {
                        *(float2*)&out[(size_t)i * n + j] =
                            make_float2(acc[mf][nf][rr * 2], acc[mf][nf][rr * 2 + 1]);
                    } else if (j < n) {
                        out[(size_t)i * n + j] = acc[mf][nf][rr * 2];
                    }
                }
            }
        }
    }

    // ---- mirror store via smem transpose (coalesced float4 rows) ----
    if (bi != bj) {
        __syncthreads();                     // operand buffers dead; alias as fp32 staging
        float* smt = (float*)smem_raw;       // [128][132]
#pragma unroll
        for (int mf = 0; mf < 4; mf++) {
            int irel_base = warp_m * 64 + mf * 16 + g;
#pragma unroll
            for (int nf = 0; nf < 4; nf++) {
                int jrel = warp_n * 32 + nf * 8 + q * 2;
                smt[(jrel)     * 132 + irel_base]     = acc[mf][nf][0];
                smt[(jrel + 1) * 132 + irel_base]     = acc[mf][nf][1];
                smt[(jrel)     * 132 + irel_base + 8] = acc[mf][nf][2];
                smt[(jrel + 1) * 132 + irel_base + 8] = acc[mf][nf][3];
            }
        }
        __syncthreads();
        // mirror j-tile is always full (bj < bi implies j0+127 < n); i-tile may be partial
        for (int c = tid; c < 128 * 32; c += 256) {
            int jr = c >> 5;
            int i4 = (c & 31) * 4;
            int gi = i0 + i4;
            size_t off = (size_t)(j0 + jr) * n + gi;
            float4 v = *(const float4*)&smt[jr * 132 + i4];
            if (gi + 3 < n) {
                *(float4*)&out[off] = v;
            } else {
                float a[4] = {v.x, v.y, v.z, v.w};
#pragma unroll
                for (int u = 0; u < 4; u++)
                    if (gi + u < n) out[off + u] = a[u];
            }
        }
    }
}

// ---------------- launch ----------------
extern "C" void kernel_launch(void* const* d_in, const int* in_sizes, int n_in,
                              void* d_out, int out_size) {
    const float* features = (const float*)d_in[0];
    const int*   src      = (const int*)d_in[1];
    const int*   dst      = (const int*)d_in[2];
    const float* noise    = (const float*)d_in[3];
    const float* W1       = (const float*)d_in[4];
    const float* b1       = (const float*)d_in[5];
    const float* W2       = (const float*)d_in[6];
    const float* b2       = (const float*)d_in[7];
    const float* W3       = (const float*)d_in[8];
    const float* b3       = (const float*)d_in[9];
    int N = in_sizes[0] / IN_DIM;
    int E = in_sizes[1];
    float* out = (float*)d_out;

    cudaFuncSetAttribute(final_kernel, cudaFuncAttributeMaxDynamicSharedMemorySize, SM_TOTAL);

    zero_kernel<<<(N + 255) / 256, 256>>>(N);
    degree_kernel<<<(E + 255) / 256, 256>>>(src, dst, E);
    rs_kernel<<<(N + 255) / 256, 256>>>(N);
    scan_kernel<<<1, 1024>>>(N);
    perm_kernel<<<(E + 255) / 256, 256>>>(src, dst, E);

    dim3 g1((N + 63) / 64, H1 / 64);
    gemm1_kernel<<<g1, 256>>>(features, W1, N);
    agg1_kernel<<<N, 128>>>(b1);
    gemm23_kernel<<<g1, 256>>>(W2, W3, N);
    aggz_kernel<<<N, 128>>>(b2, b3, noise);

    int T = (N + 127) / 128;
    final_kernel<<<T * (T + 1) / 2, 256, SM_TOTAL>>>(out, N);
}

// round 8
// speedup vs baseline: 1.7948x; 1.1999x over previous
#include <cuda_runtime.h>
#include <cuda_bf16.h>
#include <cstdint>

#define MAXN 10000
#define MAXE 320000
#define IN_DIM 512
#define H1 256
#define H2 128

// ---------------- scratch (device globals; no allocation allowed) ----------------
__device__ int   g_deg_out[MAXN];
__device__ int   g_deg_in[MAXN];
__device__ int   g_cnt[MAXN];
__device__ int   g_alloc;
__device__ float g_rs_out[MAXN];
__device__ float g_rs_in[MAXN];
__device__ int   g_row_off[MAXN];
__device__ int   g_perm_src[MAXE];
__device__ float g_y1[MAXN * H1];    // (x*rs_out) @ W1
__device__ float g_y23[MAXN * H1];   // (h*rs_out) @ [W2|W3]
__device__ __align__(16) __nv_bfloat16 g_ha_hi[MAXN * H1];  // (h*rs_out) bf16 hi
__device__ __align__(16) __nv_bfloat16 g_ha_lo[MAXN * H1];  // (h*rs_out) bf16 lo
__device__ __align__(16) __nv_bfloat16 g_w1t_hi[H1 * IN_DIM];   // W1^T [256][512]
__device__ __align__(16) __nv_bfloat16 g_w1t_lo[H1 * IN_DIM];
__device__ __align__(16) __nv_bfloat16 g_w23t_hi[H1 * H1];      // [W2|W3]^T [256][256]
__device__ __align__(16) __nv_bfloat16 g_w23t_lo[H1 * H1];
__device__ __align__(16) __nv_bfloat16 g_zhi[MAXN * H2];
__device__ __align__(16) __nv_bfloat16 g_zlo[MAXN * H2];

// ---------------- helpers ----------------
__device__ __forceinline__ float sigm(float x) {
    return 1.0f / (1.0f + __expf(-x));
}
__device__ __forceinline__ void bsplit(float v, __nv_bfloat16& hi, __nv_bfloat16& lo) {
    hi = __float2bfloat16(v);
    lo = __float2bfloat16(v - __bfloat162float(hi));
}
__device__ __forceinline__ uint32_t smem_u32(const void* p) {
    uint32_t a;
    asm("{ .reg .u64 t; cvta.to.shared.u64 t, %1; cvt.u32.u64 %0, t; }" : "=r"(a) : "l"(p));
    return a;
}
__device__ __forceinline__ void ldsm_x4(uint32_t a[4], uint32_t addr) {
    asm volatile("ldmatrix.sync.aligned.m8n8.x4.shared.b16 {%0,%1,%2,%3}, [%4];"
        : "=r"(a[0]), "=r"(a[1]), "=r"(a[2]), "=r"(a[3]) : "r"(addr));
}
__device__ __forceinline__ void ldsm_x2(uint32_t b[2], uint32_t addr) {
    asm volatile("ldmatrix.sync.aligned.m8n8.x2.shared.b16 {%0,%1}, [%2];"
        : "=r"(b[0]), "=r"(b[1]) : "r"(addr));
}
__device__ __forceinline__ void mma_bf16(float d[4], const uint32_t a[4], const uint32_t b[2]) {
    asm volatile("mma.sync.aligned.m16n8k16.row.col.f32.bf16.bf16.f32 "
        "{%0,%1,%2,%3}, {%4,%5,%6,%7}, {%8,%9}, {%0,%1,%2,%3};"
        : "+f"(d[0]), "+f"(d[1]), "+f"(d[2]), "+f"(d[3])
        : "r"(a[0]), "r"(a[1]), "r"(a[2]), "r"(a[3]), "r"(b[0]), "r"(b[1]));
}
__device__ __forceinline__ uint32_t pack_bf2(__nv_bfloat16 a, __nv_bfloat16 b) {
    __nv_bfloat162 v(a, b);
    return *(uint32_t*)&v;
}

// ---------------- small setup kernels ----------------
__global__ void zero_kernel(int n) {
    int i = blockIdx.x * blockDim.x + threadIdx.x;
    if (i < n) { g_deg_out[i] = 0; g_deg_in[i] = 0; g_cnt[i] = 0; }
    if (i == 0) g_alloc = 0;
}

__global__ void degree_kernel(const int* __restrict__ src, const int* __restrict__ dst, int e) {
    int i = blockIdx.x * blockDim.x + threadIdx.x;
    if (i < e) {
        atomicAdd(&g_deg_out[src[i]], 1);
        atomicAdd(&g_deg_in[dst[i]], 1);
    }
}

// rsqrt of degrees + order-free CSR segment allocation
__global__ void rs_alloc_kernel(int n) {
    int i = blockIdx.x * blockDim.x + threadIdx.x;
    if (i < n) {
        int dIn = g_deg_in[i];
        g_rs_out[i] = rsqrtf(fmaxf((float)g_deg_out[i], 1.0f));
        g_rs_in[i]  = rsqrtf(fmaxf((float)dIn, 1.0f));
        g_row_off[i] = atomicAdd(&g_alloc, dIn);
    }
}

__global__ void perm_kernel(const int* __restrict__ src, const int* __restrict__ dst, int e) {
    int i = blockIdx.x * blockDim.x + threadIdx.x;
    if (i < e) {
        int d = dst[i];
        int pos = atomicAdd(&g_cnt[d], 1);
        g_perm_src[g_row_off[d] + pos] = src[i];
    }
}

// one-shot weight transpose + bf16 hi/lo split
// W1T [256n][512k] from W1 [512k][256n]; W23T [256n][256k] from W2/W3 [256k][128n]
__global__ void convw_kernel(const float* __restrict__ W1, const float* __restrict__ W2,
                             const float* __restrict__ W3) {
    int idx = blockIdx.x * blockDim.x + threadIdx.x;
    if (idx < H1 * IN_DIM) {
        int nn = idx >> 9, k = idx & 511;
        __nv_bfloat16 hi, lo;
        bsplit(W1[k * H1 + nn], hi, lo);
        g_w1t_hi[idx] = hi;
        g_w1t_lo[idx] = lo;
    } else {
        int j = idx - H1 * IN_DIM;
        if (j < H1 * H1) {
            int nn = j >> 8, k = j & 255;
            float v = (nn < H2) ? W2[k * H2 + nn] : W3[k * H2 + (nn - H2)];
            __nv_bfloat16 hi, lo;
            bsplit(v, hi, lo);
            g_w23t_hi[j] = hi;
            g_w23t_lo[j] = lo;
        }
    }
}

// ---------------- HMMA GEMM smem geometry ----------------
// row pad 144B: 64 bf16 (128B) + 16B pad -> 8 ldsm rows tile the 32 banks exactly
#define ROWB_G 144
#define GBUF (128 * ROWB_G)            // 18432
#define GA_HI 0
#define GA_LO GBUF
#define GB_HI (2 * GBUF)
#define GB_LO (3 * GBUF)
#define G_TOTAL (4 * GBUF)             // 73728

// ---------------- GEMM1: y1 = (X*rs_out) @ W1 via mma.sync, in-kernel A conversion ----------------
__global__ void __launch_bounds__(256) gemm1_hmma(const float* __restrict__ X, int M) {
    extern __shared__ char smem_raw[];
    int tid = threadIdx.x;
    int w = tid >> 5, lane = tid & 31;
    int m0 = blockIdx.x * 128, n0 = blockIdx.y * 128;
    uint32_t smb = smem_u32(smem_raw);
    int warp_m = w & 1, warp_n = w >> 1;
    uint32_t aoffA = (uint32_t)((warp_m * 64 + (lane & 15)) * ROWB_G + (lane >> 4) * 16);
    uint32_t aoffB = (uint32_t)((warp_n * 32 + (lane & 7)) * ROWB_G + ((lane >> 3) & 1) * 16);

    float acc[4][4][4] = {};

    for (int ch = 0; ch < IN_DIM / 64; ch++) {
        int k0 = ch * 64;
        __syncthreads();
        // A: 128 rows x 64 k fp32 from X, scale by rs_out, split -> smem bf16 hi/lo
#pragma unroll
        for (int q = 0; q < 8; q++) {
            int idx = q * 256 + tid;
            int row = idx >> 4, c4 = (idx & 15) * 4;
            int gi = m0 + row;
            float4 v = make_float4(0.f, 0.f, 0.f, 0.f);
            float ro = 0.f;
            if (gi < M) { v = *(const float4*)&X[gi * IN_DIM + k0 + c4]; ro = g_rs_out[gi]; }
            __nv_bfloat16 h0, l0, h1, l1, h2, l2, h3, l3;
            bsplit(v.x * ro, h0, l0); bsplit(v.y * ro, h1, l1);
            bsplit(v.z * ro, h2, l2); bsplit(v.w * ro, h3, l3);
            int off = row * ROWB_G + c4 * 2;
            *(uint2*)(smem_raw + GA_HI + off) = make_uint2(pack_bf2(h0, h1), pack_bf2(h2, h3));
            *(uint2*)(smem_raw + GA_LO + off) = make_uint2(pack_bf2(l0, l1), pack_bf2(l2, l3));
        }
        // B: 128 n-rows x 64 k bf16 from W1T
#pragma unroll
        for (int q = 0; q < 4; q++) {
            int idx = q * 256 + tid;
            int row = idx >> 3, seg = (idx & 7);
            int off = row * ROWB_G + seg * 16;
            *(uint4*)(smem_raw + GB_HI + off) = *(const uint4*)&g_w1t_hi[(n0 + row) * IN_DIM + k0 + seg * 8];
            *(uint4*)(smem_raw + GB_LO + off) = *(const uint4*)&g_w1t_lo[(n0 + row) * IN_DIM + k0 + seg * 8];
        }
        __syncthreads();
#pragma unroll
        for (int ks = 0; ks < 4; ks++) {
            uint32_t k2 = (uint32_t)(ks * 32);
            uint32_t Ahi[4][4], Bhi[4][2], Blo[4][2];
#pragma unroll
            for (int mf = 0; mf < 4; mf++)
                ldsm_x4(Ahi[mf], smb + GA_HI + aoffA + mf * (16 * ROWB_G) + k2);
#pragma unroll
            for (int nf = 0; nf < 4; nf++) {
                ldsm_x2(Bhi[nf], smb + GB_HI + aoffB + nf * (8 * ROWB_G) + k2);
                ldsm_x2(Blo[nf], smb + GB_LO + aoffB + nf * (8 * ROWB_G) + k2);
            }
#pragma unroll
            for (int mf = 0; mf < 4; mf++)
#pragma unroll
                for (int nf = 0; nf < 4; nf++) {
                    mma_bf16(acc[mf][nf], Ahi[mf], Bhi[nf]);
                    mma_bf16(acc[mf][nf], Ahi[mf], Blo[nf]);
                }
            uint32_t Alo[4][4];
#pragma unroll
            for (int mf = 0; mf < 4; mf++)
                ldsm_x4(Alo[mf], smb + GA_LO + aoffA + mf * (16 * ROWB_G) + k2);
#pragma unroll
            for (int mf = 0; mf < 4; mf++)
#pragma unroll
                for (int nf = 0; nf < 4; nf++)
                    mma_bf16(acc[mf][nf], Alo[mf], Bhi[nf]);
        }
    }
    // store y1 fp32
    int g = lane >> 2, q = lane & 3;
#pragma unroll
    for (int mf = 0; mf < 4; mf++)
#pragma unroll
        for (int rr = 0; rr < 2; rr++) {
            int i = m0 + warp_m * 64 + mf * 16 + g + rr * 8;
            if (i < M) {
#pragma unroll
                for (int nf = 0; nf < 4; nf++) {
                    int j = n0 + warp_n * 32 + nf * 8 + q * 2;
                    *(float2*)&g_y1[i * H1 + j] =
                        make_float2(acc[mf][nf][rr * 2], acc[mf][nf][rr * 2 + 1]);
                }
            }
        }
}

// ---------------- GEMM23: y23 = (h*rs_out) @ [W2|W3], bf16 A from agg1 ----------------
__global__ void __launch_bounds__(256) gemm23_hmma(int M) {
    extern __shared__ char smem_raw[];
    int tid = threadIdx.x;
    int w = tid >> 5, lane = tid & 31;
    int m0 = blockIdx.x * 128, n0 = blockIdx.y * 128;
    uint32_t smb = smem_u32(smem_raw);
    int warp_m = w & 1, warp_n = w >> 1;
    uint32_t aoffA = (uint32_t)((warp_m * 64 + (lane & 15)) * ROWB_G + (lane >> 4) * 16);
    uint32_t aoffB = (uint32_t)((warp_n * 32 + (lane & 7)) * ROWB_G + ((lane >> 3) & 1) * 16);

    float acc[4][4][4] = {};
    const uint4 zz = make_uint4(0u, 0u, 0u, 0u);

    for (int ch = 0; ch < H1 / 64; ch++) {
        int k0 = ch * 64;
        __syncthreads();
#pragma unroll
        for (int q = 0; q < 4; q++) {
            int idx = q * 256 + tid;
            int row = idx >> 3, seg = (idx & 7);
            int off = row * ROWB_G + seg * 16;
            int gi = m0 + row;
            uint4 ahi = zz, alo = zz;
            if (gi < M) {
                ahi = *(const uint4*)&g_ha_hi[gi * H1 + k0 + seg * 8];
                alo = *(const uint4*)&g_ha_lo[gi * H1 + k0 + seg * 8];
            }
            *(uint4*)(smem_raw + GA_HI + off) = ahi;
            *(uint4*)(smem_raw + GA_LO + off) = alo;
            *(uint4*)(smem_raw + GB_HI + off) = *(const uint4*)&g_w23t_hi[(n0 + row) * H1 + k0 + seg * 8];
            *(uint4*)(smem_raw + GB_LO + off) = *(const uint4*)&g_w23t_lo[(n0 + row) * H1 + k0 + seg * 8];
        }
        __syncthreads();
#pragma unroll
        for (int ks = 0; ks < 4; ks++) {
            uint32_t k2 = (uint32_t)(ks * 32);
            uint32_t Ahi[4][4], Bhi[4][2], Blo[4][2];
#pragma unroll
            for (int mf = 0; mf < 4; mf++)
                ldsm_x4(Ahi[mf], smb + GA_HI + aoffA + mf * (16 * ROWB_G) + k2);
#pragma unroll
            for (int nf = 0; nf < 4; nf++) {
                ldsm_x2(Bhi[nf], smb + GB_HI + aoffB + nf * (8 * ROWB_G) + k2);
                ldsm_x2(Blo[nf], smb + GB_LO + aoffB + nf * (8 * ROWB_G) + k2);
            }
#pragma unroll
            for (int mf = 0; mf < 4; mf++)
#pragma unroll
                for (int nf = 0; nf < 4; nf++) {
                    mma_bf16(acc[mf][nf], Ahi[mf], Bhi[nf]);
                    mma_bf16(acc[mf][nf], Ahi[mf], Blo[nf]);
                }
            uint32_t Alo[4][4];
#pragma unroll
            for (int mf = 0; mf < 4; mf++)
                ldsm_x4(Alo[mf], smb + GA_LO + aoffA + mf * (16 * ROWB_G) + k2);
#pragma unroll
            for (int mf = 0; mf < 4; mf++)
#pragma unroll
                for (int nf = 0; nf < 4; nf++)
                    mma_bf16(acc[mf][nf], Alo[mf], Bhi[nf]);
        }
    }
    int g = lane >> 2, q = lane & 3;
#pragma unroll
    for (int mf = 0; mf < 4; mf++)
#pragma unroll
        for (int rr = 0; rr < 2; rr++) {
            int i = m0 + warp_m * 64 + mf * 16 + g + rr * 8;
            if (i < M) {
#pragma unroll
                for (int nf = 0; nf < 4; nf++) {
                    int j = n0 + warp_n * 32 + nf * 8 + q * 2;
                    *(float2*)&g_y23[i * H1 + j] =
                        make_float2(acc[mf][nf][rr * 2], acc[mf][nf][rr * 2 + 1]);
                }
            }
        }
}

// ---------------- agg1: h = relu(rs_in*seg_sum(y1[src]) + b1); emit (h*rs_out) bf16 hi/lo ----------------
__global__ void agg1_kernel(const float* __restrict__ b1) {
    int d = blockIdx.x, t = threadIdx.x;
    int s = g_row_off[d], e = s + g_deg_in[d];
    float ax = 0.f, ay = 0.f;
    const float2* Y = (const float2*)g_y1;
    for (int i = s; i < e; i++) {
        int sn = g_perm_src[i];
        float2 v = Y[sn * (H1 / 2) + t];
        ax += v.x; ay += v.y;
    }
    float ri = g_rs_in[d];
    float ro = g_rs_out[d];
    float h0 = fmaxf(ax * ri + b1[2 * t], 0.f) * ro;
    float h1 = fmaxf(ay * ri + b1[2 * t + 1], 0.f) * ro;
    __nv_bfloat16 hi0, lo0, hi1, lo1;
    bsplit(h0, hi0, lo0);
    bsplit(h1, hi1, lo1);
    ((uint32_t*)g_ha_hi)[d * (H1 / 2) + t] = pack_bf2(hi0, hi1);
    ((uint32_t*)g_ha_lo)[d * (H1 / 2) + t] = pack_bf2(lo0, lo1);
}

// ---------------- aggz: s = rs_in*seg_sum(y23[src]); z = (s0+b2) + noise*exp(s1+b3) ----------------
__global__ void aggz_kernel(const float* __restrict__ b2, const float* __restrict__ b3,
                            const float* __restrict__ noise) {
    __shared__ float sm[H1];
    int d = blockIdx.x, t = threadIdx.x;
    int s = g_row_off[d], e = s + g_deg_in[d];
    float ax = 0.f, ay = 0.f;
    const float2* Y = (const float2*)g_y23;
    for (int i = s; i < e; i++) {
        int sn = g_perm_src[i];
        float2 v = Y[sn * (H1 / 2) + t];
        ax += v.x; ay += v.y;
    }
    float ri = g_rs_in[d];
    sm[2 * t] = ax * ri;
    sm[2 * t + 1] = ay * ri;
    __syncthreads();
    if (t < 64) {
#pragma unroll
        for (int q = 0; q < 2; q++) {
            int c = 2 * t + q;
            float mean = sm[c] + b2[c];
            float ls = sm[c + H2] + b3[c];
            float zv = mean + noise[d * H2 + c] * expf(ls);
            __nv_bfloat16 hi, lo;
            bsplit(zv, hi, lo);
            g_zhi[d * H2 + c] = hi;
            g_zlo[d * H2 + c] = lo;
        }
    }
}

// ---------------- final decoder: mma.sync bf16 hi/lo, 128x128 tiles ----------------
#define ROWB 272
#define BUF_SZ (128 * ROWB)
#define SM_HI_I 0
#define SM_LO_I (BUF_SZ)
#define SM_HI_J (2 * BUF_SZ)
#define SM_LO_J (3 * BUF_SZ)
#define SM_TOTAL (4 * BUF_SZ)

__global__ void __launch_bounds__(256) final_kernel(float* __restrict__ out, int n) {
    extern __shared__ char smem_raw[];
    int tid = threadIdx.x;
    int w = tid >> 5, lane = tid & 31;

    int p = blockIdx.x;
    int bi = (int)((sqrtf(8.0f * (float)p + 1.0f) - 1.0f) * 0.5f);
    while ((bi + 1) * (bi + 2) / 2 <= p) bi++;
    while (bi * (bi + 1) / 2 > p) bi--;
    int bj = p - bi * (bi + 1) / 2;
    int i0 = bi * 128, j0 = bj * 128;

    const uint4 zz = make_uint4(0u, 0u, 0u, 0u);
    for (int c = tid; c < 2048; c += 256) {
        int row = c >> 4, seg = c & 15;
        int off = row * ROWB + seg * 16;
        int gi = i0 + row, gj = j0 + row;
        uint4 hi_i = zz, lo_i = zz, hi_j = zz, lo_j = zz;
        if (gi < n) {
            hi_i = *(const uint4*)&g_zhi[gi * H2 + seg * 8];
            lo_i = *(const uint4*)&g_zlo[gi * H2 + seg * 8];
        }
        if (gj < n) {
            hi_j = *(const uint4*)&g_zhi[gj * H2 + seg * 8];
            lo_j = *(const uint4*)&g_zlo[gj * H2 + seg * 8];
        }
        *(uint4*)(smem_raw + SM_HI_I + off) = hi_i;
        *(uint4*)(smem_raw + SM_LO_I + off) = lo_i;
        *(uint4*)(smem_raw + SM_HI_J + off) = hi_j;
        *(uint4*)(smem_raw + SM_LO_J + off) = lo_j;
    }
    __syncthreads();

    uint32_t smb = smem_u32(smem_raw);
    int warp_m = w & 1, warp_n = w >> 1;
    uint32_t aoffA = (uint32_t)((warp_m * 64 + (lane & 15)) * ROWB + (lane >> 4) * 16);
    uint32_t aoffB = (uint32_t)((warp_n * 32 + (lane & 7)) * ROWB + ((lane >> 3) & 1) * 16);

    float acc[4][4][4] = {};

    for (int ks = 0; ks < 8; ks++) {
        uint32_t k2 = (uint32_t)(ks * 32);
        uint32_t Ahi[4][4], Bhi[4][2], Blo[4][2];
#pragma unroll
        for (int mf = 0; mf < 4; mf++)
            ldsm_x4(Ahi[mf], smb + SM_HI_I + aoffA + mf * (16 * ROWB) + k2);
#pragma unroll
        for (int nf = 0; nf < 4; nf++) {
            ldsm_x2(Bhi[nf], smb + SM_HI_J + aoffB + nf * (8 * ROWB) + k2);
            ldsm_x2(Blo[nf], smb + SM_LO_J + aoffB + nf * (8 * ROWB) + k2);
        }
#pragma unroll
        for (int mf = 0; mf < 4; mf++)
#pragma unroll
            for (int nf = 0; nf < 4; nf++) {
                mma_bf16(acc[mf][nf], Ahi[mf], Bhi[nf]);
                mma_bf16(acc[mf][nf], Ahi[mf], Blo[nf]);
            }
        uint32_t Alo[4][4];
#pragma unroll
        for (int mf = 0; mf < 4; mf++)
            ldsm_x4(Alo[mf], smb + SM_LO_I + aoffA + mf * (16 * ROWB) + k2);
#pragma unroll
        for (int mf = 0; mf < 4; mf++)
#pragma unroll
            for (int nf = 0; nf < 4; nf++)
                mma_bf16(acc[mf][nf], Alo[mf], Bhi[nf]);
    }

#pragma unroll
    for (int mf = 0; mf < 4; mf++)
#pragma unroll
        for (int nf = 0; nf < 4; nf++)
#pragma unroll
            for (int r = 0; r < 4; r++)
                acc[mf][nf][r] = sigm(acc[mf][nf][r]);

    int g = lane >> 2, q = lane & 3;

#pragma unroll
    for (int mf = 0; mf < 4; mf++) {
#pragma unroll
        for (int rr = 0; rr < 2; rr++) {
            int i = i0 + warp_m * 64 + mf * 16 + g + rr * 8;
            if (i < n) {
#pragma unroll
                for (int nf = 0; nf < 4; nf++) {
                    int j = j0 + warp_n * 32 + nf * 8 + q * 2;
                    if (j + 1 < n) {
                        *(float2*)&out[(size_t)i * n + j] =
                            make_float2(acc[mf][nf][rr * 2], acc[mf][nf][rr * 2 + 1]);
                    } else if (j < n) {
                        out[(size_t)i * n + j] = acc[mf][nf][rr * 2];
                    }
                }
            }
        }
    }

    if (bi != bj) {
        __syncthreads();
        float* smt = (float*)smem_raw;
#pragma unroll
        for (int mf = 0; mf < 4; mf++) {
            int irel_base = warp_m * 64 + mf * 16 + g;
#pragma unroll
            for (int nf = 0; nf < 4; nf++) {
                int jrel = warp_n * 32 + nf * 8 + q * 2;
                smt[(jrel)     * 132 + irel_base]     = acc[mf][nf][0];
                smt[(jrel + 1) * 132 + irel_base]     = acc[mf][nf][1];
                smt[(jrel)     * 132 + irel_base + 8] = acc[mf][nf][2];
                smt[(jrel + 1) * 132 + irel_base + 8] = acc[mf][nf][3];
            }
        }
        __syncthreads();
        for (int c = tid; c < 128 * 32; c += 256) {
            int jr = c >> 5;
            int i4 = (c & 31) * 4;
            int gi = i0 + i4;
            size_t off = (size_t)(j0 + jr) * n + gi;
            float4 v = *(const float4*)&smt[jr * 132 + i4];
            if (gi + 3 < n) {
                *(float4*)&out[off] = v;
            } else {
                float a[4] = {v.x, v.y, v.z, v.w};
#pragma unroll
                for (int u = 0; u < 4; u++)
                    if (gi + u < n) out[off + u] = a[u];
            }
        }
    }
}

// ---------------- launch ----------------
extern "C" void kernel_launch(void* const* d_in, const int* in_sizes, int n_in,
                              void* d_out, int out_size) {
    const float* features = (const float*)d_in[0];
    const int*   src      = (const int*)d_in[1];
    const int*   dst      = (const int*)d_in[2];
    const float* noise    = (const float*)d_in[3];
    const float* W1       = (const float*)d_in[4];
    const float* b1       = (const float*)d_in[5];
    const float* W2       = (const float*)d_in[6];
    const float* b2       = (const float*)d_in[7];
    const float* W3       = (const float*)d_in[8];
    const float* b3       = (const float*)d_in[9];
    int N = in_sizes[0] / IN_DIM;
    int E = in_sizes[1];
    float* out = (float*)d_out;

    cudaFuncSetAttribute(final_kernel, cudaFuncAttributeMaxDynamicSharedMemorySize, SM_TOTAL);
    cudaFuncSetAttribute(gemm1_hmma, cudaFuncAttributeMaxDynamicSharedMemorySize, G_TOTAL);
    cudaFuncSetAttribute(gemm23_hmma, cudaFuncAttributeMaxDynamicSharedMemorySize, G_TOTAL);

    zero_kernel<<<(N + 255) / 256, 256>>>(N);
    degree_kernel<<<(E + 255) / 256, 256>>>(src, dst, E);
    rs_alloc_kernel<<<(N + 255) / 256, 256>>>(N);
    perm_kernel<<<(E + 255) / 256, 256>>>(src, dst, E);
    convw_kernel<<<(H1 * IN_DIM + H1 * H1 + 255) / 256, 256>>>(W1, W2, W3);

    dim3 gg((N + 127) / 128, 2);
    gemm1_hmma<<<gg, 256, G_TOTAL>>>(features, N);
    agg1_kernel<<<N, 128>>>(b1);
    gemm23_hmma<<<gg, 256, G_TOTAL>>>(N);
    aggz_kernel<<<N, 128>>>(b2, b3, noise);

    int T = (N + 127) / 128;
    final_kernel<<<T * (T + 1) / 2, 256, SM_TOTAL>>>(out, N);
}

// round 9
// speedup vs baseline: 2.1588x; 1.2028x over previous
#include <cuda_runtime.h>
#include <cuda_bf16.h>
#include <cstdint>

#define MAXN 10000
#define MAXE 320000
#define IN_DIM 512
#define H1 256
#define H2 128

// ---------------- scratch (device globals; no allocation allowed) ----------------
__device__ int   g_deg_out[MAXN];
__device__ int   g_deg_in[MAXN];
__device__ int   g_cnt[MAXN];
__device__ int   g_alloc;
__device__ float g_rs_out[MAXN];
__device__ float g_rs_in[MAXN];
__device__ int   g_row_off[MAXN];
__device__ int   g_perm_src[MAXE];
__device__ float g_y1[MAXN * H1];    // (x*rs_out) @ W1
__device__ float g_y23[MAXN * H1];   // (h*rs_out) @ [W2|W3]
__device__ __align__(16) __nv_bfloat16 g_ha_hi[MAXN * H1];  // (h*rs_out) bf16 hi
__device__ __align__(16) __nv_bfloat16 g_ha_lo[MAXN * H1];  // (h*rs_out) bf16 lo
__device__ __align__(16) __nv_bfloat16 g_w1t_hi[H1 * IN_DIM];   // W1^T [256][512]
__device__ __align__(16) __nv_bfloat16 g_w1t_lo[H1 * IN_DIM];
__device__ __align__(16) __nv_bfloat16 g_w23t_hi[H1 * H1];      // [W2|W3]^T [256][256]
__device__ __align__(16) __nv_bfloat16 g_w23t_lo[H1 * H1];
__device__ __align__(16) __nv_bfloat16 g_zhi[MAXN * H2];
__device__ __align__(16) __nv_bfloat16 g_zlo[MAXN * H2];

// ---------------- helpers ----------------
__device__ __forceinline__ float sigm(float x) {
    return 1.0f / (1.0f + __expf(-x));
}
__device__ __forceinline__ void bsplit(float v, __nv_bfloat16& hi, __nv_bfloat16& lo) {
    hi = __float2bfloat16(v);
    lo = __float2bfloat16(v - __bfloat162float(hi));
}
__device__ __forceinline__ uint32_t smem_u32(const void* p) {
    uint32_t a;
    asm("{ .reg .u64 t; cvta.to.shared.u64 t, %1; cvt.u32.u64 %0, t; }" : "=r"(a) : "l"(p));
    return a;
}
__device__ __forceinline__ void ldsm_x4(uint32_t a[4], uint32_t addr) {
    asm volatile("ldmatrix.sync.aligned.m8n8.x4.shared.b16 {%0,%1,%2,%3}, [%4];"
        : "=r"(a[0]), "=r"(a[1]), "=r"(a[2]), "=r"(a[3]) : "r"(addr));
}
__device__ __forceinline__ void ldsm_x2(uint32_t b[2], uint32_t addr) {
    asm volatile("ldmatrix.sync.aligned.m8n8.x2.shared.b16 {%0,%1}, [%2];"
        : "=r"(b[0]), "=r"(b[1]) : "r"(addr));
}
__device__ __forceinline__ void mma_bf16(float d[4], const uint32_t a[4], const uint32_t b[2]) {
    asm volatile("mma.sync.aligned.m16n8k16.row.col.f32.bf16.bf16.f32 "
        "{%0,%1,%2,%3}, {%4,%5,%6,%7}, {%8,%9}, {%0,%1,%2,%3};"
        : "+f"(d[0]), "+f"(d[1]), "+f"(d[2]), "+f"(d[3])
        : "r"(a[0]), "r"(a[1]), "r"(a[2]), "r"(a[3]), "r"(b[0]), "r"(b[1]));
}
__device__ __forceinline__ uint32_t pack_bf2(__nv_bfloat16 a, __nv_bfloat16 b) {
    __nv_bfloat162 v(a, b);
    return *(uint32_t*)&v;
}

// ---------------- small setup kernels ----------------
__global__ void zero_kernel(int n) {
    int i = blockIdx.x * blockDim.x + threadIdx.x;
    if (i < n) { g_deg_out[i] = 0; g_deg_in[i] = 0; g_cnt[i] = 0; }
    if (i == 0) g_alloc = 0;
}

__global__ void degree_kernel(const int* __restrict__ src, const int* __restrict__ dst, int e) {
    int i = blockIdx.x * blockDim.x + threadIdx.x;
    if (i < e) {
        atomicAdd(&g_deg_out[src[i]], 1);
        atomicAdd(&g_deg_in[dst[i]], 1);
    }
}

__global__ void rs_alloc_kernel(int n) {
    int i = blockIdx.x * blockDim.x + threadIdx.x;
    if (i < n) {
        int dIn = g_deg_in[i];
        g_rs_out[i] = rsqrtf(fmaxf((float)g_deg_out[i], 1.0f));
        g_rs_in[i]  = rsqrtf(fmaxf((float)dIn, 1.0f));
        g_row_off[i] = atomicAdd(&g_alloc, dIn);
    }
}

__global__ void perm_kernel(const int* __restrict__ src, const int* __restrict__ dst, int e) {
    int i = blockIdx.x * blockDim.x + threadIdx.x;
    if (i < e) {
        int d = dst[i];
        int pos = atomicAdd(&g_cnt[d], 1);
        g_perm_src[g_row_off[d] + pos] = src[i];
    }
}

// one-shot weight transpose + bf16 hi/lo split
__global__ void convw_kernel(const float* __restrict__ W1, const float* __restrict__ W2,
                             const float* __restrict__ W3) {
    int idx = blockIdx.x * blockDim.x + threadIdx.x;
    if (idx < H1 * IN_DIM) {
        int nn = idx >> 9, k = idx & 511;
        __nv_bfloat16 hi, lo;
        bsplit(W1[k * H1 + nn], hi, lo);
        g_w1t_hi[idx] = hi;
        g_w1t_lo[idx] = lo;
    } else {
        int j = idx - H1 * IN_DIM;
        if (j < H1 * H1) {
            int nn = j >> 8, k = j & 255;
            float v = (nn < H2) ? W2[k * H2 + nn] : W3[k * H2 + (nn - H2)];
            __nv_bfloat16 hi, lo;
            bsplit(v, hi, lo);
            g_w23t_hi[j] = hi;
            g_w23t_lo[j] = lo;
        }
    }
}

// ---------------- HMMA GEMM smem geometry ----------------
#define ROWB_G 144
#define GBUF (128 * ROWB_G)
#define GA_HI 0
#define GA_LO GBUF
#define GB_HI (2 * GBUF)
#define GB_LO (3 * GBUF)
#define G_TOTAL (4 * GBUF)             // 73728

// ---------------- GEMM1: y1 = (X*rs_out) @ W1 ----------------
__global__ void __launch_bounds__(256) gemm1_hmma(const float* __restrict__ X, int M) {
    extern __shared__ char smem_raw[];
    int tid = threadIdx.x;
    int w = tid >> 5, lane = tid & 31;
    int m0 = blockIdx.x * 128, n0 = blockIdx.y * 128;
    uint32_t smb = smem_u32(smem_raw);
    int warp_m = w & 1, warp_n = w >> 1;
    uint32_t aoffA = (uint32_t)((warp_m * 64 + (lane & 15)) * ROWB_G + (lane >> 4) * 16);
    uint32_t aoffB = (uint32_t)((warp_n * 32 + (lane & 7)) * ROWB_G + ((lane >> 3) & 1) * 16);

    float acc[4][4][4] = {};

    for (int ch = 0; ch < IN_DIM / 64; ch++) {
        int k0 = ch * 64;
        __syncthreads();
#pragma unroll
        for (int q = 0; q < 8; q++) {
            int idx = q * 256 + tid;
            int row = idx >> 4, c4 = (idx & 15) * 4;
            int gi = m0 + row;
            float4 v = make_float4(0.f, 0.f, 0.f, 0.f);
            float ro = 0.f;
            if (gi < M) { v = *(const float4*)&X[gi * IN_DIM + k0 + c4]; ro = g_rs_out[gi]; }
            __nv_bfloat16 h0, l0, h1, l1, h2, l2, h3, l3;
            bsplit(v.x * ro, h0, l0); bsplit(v.y * ro, h1, l1);
            bsplit(v.z * ro, h2, l2); bsplit(v.w * ro, h3, l3);
            int off = row * ROWB_G + c4 * 2;
            *(uint2*)(smem_raw + GA_HI + off) = make_uint2(pack_bf2(h0, h1), pack_bf2(h2, h3));
            *(uint2*)(smem_raw + GA_LO + off) = make_uint2(pack_bf2(l0, l1), pack_bf2(l2, l3));
        }
#pragma unroll
        for (int q = 0; q < 4; q++) {
            int idx = q * 256 + tid;
            int row = idx >> 3, seg = (idx & 7);
            int off = row * ROWB_G + seg * 16;
            *(uint4*)(smem_raw + GB_HI + off) = *(const uint4*)&g_w1t_hi[(n0 + row) * IN_DIM + k0 + seg * 8];
            *(uint4*)(smem_raw + GB_LO + off) = *(const uint4*)&g_w1t_lo[(n0 + row) * IN_DIM + k0 + seg * 8];
        }
        __syncthreads();
#pragma unroll
        for (int ks = 0; ks < 4; ks++) {
            uint32_t k2 = (uint32_t)(ks * 32);
            uint32_t Ahi[4][4], Bhi[4][2], Blo[4][2];
#pragma unroll
            for (int mf = 0; mf < 4; mf++)
                ldsm_x4(Ahi[mf], smb + GA_HI + aoffA + mf * (16 * ROWB_G) + k2);
#pragma unroll
            for (int nf = 0; nf < 4; nf++) {
                ldsm_x2(Bhi[nf], smb + GB_HI + aoffB + nf * (8 * ROWB_G) + k2);
                ldsm_x2(Blo[nf], smb + GB_LO + aoffB + nf * (8 * ROWB_G) + k2);
            }
#pragma unroll
            for (int mf = 0; mf < 4; mf++)
#pragma unroll
                for (int nf = 0; nf < 4; nf++) {
                    mma_bf16(acc[mf][nf], Ahi[mf], Bhi[nf]);
                    mma_bf16(acc[mf][nf], Ahi[mf], Blo[nf]);
                }
            uint32_t Alo[4][4];
#pragma unroll
            for (int mf = 0; mf < 4; mf++)
                ldsm_x4(Alo[mf], smb + GA_LO + aoffA + mf * (16 * ROWB_G) + k2);
#pragma unroll
            for (int mf = 0; mf < 4; mf++)
#pragma unroll
                for (int nf = 0; nf < 4; nf++)
                    mma_bf16(acc[mf][nf], Alo[mf], Bhi[nf]);
        }
    }
    int g = lane >> 2, q = lane & 3;
#pragma unroll
    for (int mf = 0; mf < 4; mf++)
#pragma unroll
        for (int rr = 0; rr < 2; rr++) {
            int i = m0 + warp_m * 64 + mf * 16 + g + rr * 8;
            if (i < M) {
#pragma unroll
                for (int nf = 0; nf < 4; nf++) {
                    int j = n0 + warp_n * 32 + nf * 8 + q * 2;
                    *(float2*)&g_y1[i * H1 + j] =
                        make_float2(acc[mf][nf][rr * 2], acc[mf][nf][rr * 2 + 1]);
                }
            }
        }
}

// ---------------- GEMM23: y23 = (h*rs_out) @ [W2|W3] ----------------
__global__ void __launch_bounds__(256) gemm23_hmma(int M) {
    extern __shared__ char smem_raw[];
    int tid = threadIdx.x;
    int w = tid >> 5, lane = tid & 31;
    int m0 = blockIdx.x * 128, n0 = blockIdx.y * 128;
    uint32_t smb = smem_u32(smem_raw);
    int warp_m = w & 1, warp_n = w >> 1;
    uint32_t aoffA = (uint32_t)((warp_m * 64 + (lane & 15)) * ROWB_G + (lane >> 4) * 16);
    uint32_t aoffB = (uint32_t)((warp_n * 32 + (lane & 7)) * ROWB_G + ((lane >> 3) & 1) * 16);

    float acc[4][4][4] = {};
    const uint4 zz = make_uint4(0u, 0u, 0u, 0u);

    for (int ch = 0; ch < H1 / 64; ch++) {
        int k0 = ch * 64;
        __syncthreads();
#pragma unroll
        for (int q = 0; q < 4; q++) {
            int idx = q * 256 + tid;
            int row = idx >> 3, seg = (idx & 7);
            int off = row * ROWB_G + seg * 16;
            int gi = m0 + row;
            uint4 ahi = zz, alo = zz;
            if (gi < M) {
                ahi = *(const uint4*)&g_ha_hi[gi * H1 + k0 + seg * 8];
                alo = *(const uint4*)&g_ha_lo[gi * H1 + k0 + seg * 8];
            }
            *(uint4*)(smem_raw + GA_HI + off) = ahi;
            *(uint4*)(smem_raw + GA_LO + off) = alo;
            *(uint4*)(smem_raw + GB_HI + off) = *(const uint4*)&g_w23t_hi[(n0 + row) * H1 + k0 + seg * 8];
            *(uint4*)(smem_raw + GB_LO + off) = *(const uint4*)&g_w23t_lo[(n0 + row) * H1 + k0 + seg * 8];
        }
        __syncthreads();
#pragma unroll
        for (int ks = 0; ks < 4; ks++) {
            uint32_t k2 = (uint32_t)(ks * 32);
            uint32_t Ahi[4][4], Bhi[4][2], Blo[4][2];
#pragma unroll
            for (int mf = 0; mf < 4; mf++)
                ldsm_x4(Ahi[mf], smb + GA_HI + aoffA + mf * (16 * ROWB_G) + k2);
#pragma unroll
            for (int nf = 0; nf < 4; nf++) {
                ldsm_x2(Bhi[nf], smb + GB_HI + aoffB + nf * (8 * ROWB_G) + k2);
                ldsm_x2(Blo[nf], smb + GB_LO + aoffB + nf * (8 * ROWB_G) + k2);
            }
#pragma unroll
            for (int mf = 0; mf < 4; mf++)
#pragma unroll
                for (int nf = 0; nf < 4; nf++) {
                    mma_bf16(acc[mf][nf], Ahi[mf], Bhi[nf]);
                    mma_bf16(acc[mf][nf], Ahi[mf], Blo[nf]);
                }
            uint32_t Alo[4][4];
#pragma unroll
            for (int mf = 0; mf < 4; mf++)
                ldsm_x4(Alo[mf], smb + GA_LO + aoffA + mf * (16 * ROWB_G) + k2);
#pragma unroll
            for (int mf = 0; mf < 4; mf++)
#pragma unroll
                for (int nf = 0; nf < 4; nf++)
                    mma_bf16(acc[mf][nf], Alo[mf], Bhi[nf]);
        }
    }
    int g = lane >> 2, q = lane & 3;
#pragma unroll
    for (int mf = 0; mf < 4; mf++)
#pragma unroll
        for (int rr = 0; rr < 2; rr++) {
            int i = m0 + warp_m * 64 + mf * 16 + g + rr * 8;
            if (i < M) {
#pragma unroll
                for (int nf = 0; nf < 4; nf++) {
                    int j = n0 + warp_n * 32 + nf * 8 + q * 2;
                    *(float2*)&g_y23[i * H1 + j] =
                        make_float2(acc[mf][nf][rr * 2], acc[mf][nf][rr * 2 + 1]);
                }
            }
        }
}

// ---------------- agg1: unroll-4 gather; h = relu(rs_in*sum + b1); emit (h*rs_out) bf16 ----------------
__global__ void agg1_kernel(const float* __restrict__ b1) {
    int d = blockIdx.x, t = threadIdx.x;
    int s = g_row_off[d], e = s + g_deg_in[d];
    const float2* Y = (const float2*)g_y1;
    float2 a0 = make_float2(0.f, 0.f), a1 = a0, a2 = a0, a3 = a0;
    int i = s;
    for (; i + 3 < e; i += 4) {
        int s0 = g_perm_src[i], s1 = g_perm_src[i + 1];
        int s2 = g_perm_src[i + 2], s3 = g_perm_src[i + 3];
        float2 v0 = Y[s0 * (H1 / 2) + t];
        float2 v1 = Y[s1 * (H1 / 2) + t];
        float2 v2 = Y[s2 * (H1 / 2) + t];
        float2 v3 = Y[s3 * (H1 / 2) + t];
        a0.x += v0.x; a0.y += v0.y;
        a1.x += v1.x; a1.y += v1.y;
        a2.x += v2.x; a2.y += v2.y;
        a3.x += v3.x; a3.y += v3.y;
    }
    for (; i < e; i++) {
        int sn = g_perm_src[i];
        float2 v = Y[sn * (H1 / 2) + t];
        a0.x += v.x; a0.y += v.y;
    }
    float ax = (a0.x + a1.x) + (a2.x + a3.x);
    float ay = (a0.y + a1.y) + (a2.y + a3.y);
    float ri = g_rs_in[d];
    float ro = g_rs_out[d];
    float h0 = fmaxf(ax * ri + b1[2 * t], 0.f) * ro;
    float h1 = fmaxf(ay * ri + b1[2 * t + 1], 0.f) * ro;
    __nv_bfloat16 hi0, lo0, hi1, lo1;
    bsplit(h0, hi0, lo0);
    bsplit(h1, hi1, lo1);
    ((uint32_t*)g_ha_hi)[d * (H1 / 2) + t] = pack_bf2(hi0, hi1);
    ((uint32_t*)g_ha_lo)[d * (H1 / 2) + t] = pack_bf2(lo0, lo1);
}

// ---------------- aggz: unroll-4 gather; z = (s0+b2) + noise*exp(s1+b3) ----------------
__global__ void aggz_kernel(const float* __restrict__ b2, const float* __restrict__ b3,
                            const float* __restrict__ noise) {
    __shared__ float sm[H1];
    int d = blockIdx.x, t = threadIdx.x;
    int s = g_row_off[d], e = s + g_deg_in[d];
    const float2* Y = (const float2*)g_y23;
    float2 a0 = make_float2(0.f, 0.f), a1 = a0, a2 = a0, a3 = a0;
    int i = s;
    for (; i + 3 < e; i += 4) {
        int s0 = g_perm_src[i], s1 = g_perm_src[i + 1];
        int s2 = g_perm_src[i + 2], s3 = g_perm_src[i + 3];
        float2 v0 = Y[s0 * (H1 / 2) + t];
        float2 v1 = Y[s1 * (H1 / 2) + t];
        float2 v2 = Y[s2 * (H1 / 2) + t];
        float2 v3 = Y[s3 * (H1 / 2) + t];
        a0.x += v0.x; a0.y += v0.y;
        a1.x += v1.x; a1.y += v1.y;
        a2.x += v2.x; a2.y += v2.y;
        a3.x += v3.x; a3.y += v3.y;
    }
    for (; i < e; i++) {
        int sn = g_perm_src[i];
        float2 v = Y[sn * (H1 / 2) + t];
        a0.x += v.x; a0.y += v.y;
    }
    float ax = (a0.x + a1.x) + (a2.x + a3.x);
    float ay = (a0.y + a1.y) + (a2.y + a3.y);
    float ri = g_rs_in[d];
    sm[2 * t] = ax * ri;
    sm[2 * t + 1] = ay * ri;
    __syncthreads();
    if (t < 64) {
#pragma unroll
        for (int q = 0; q < 2; q++) {
            int c = 2 * t + q;
            float mean = sm[c] + b2[c];
            float ls = sm[c + H2] + b3[c];
            float zv = mean + noise[d * H2 + c] * expf(ls);
            __nv_bfloat16 hi, lo;
            bsplit(zv, hi, lo);
            g_zhi[d * H2 + c] = hi;
            g_zlo[d * H2 + c] = lo;
        }
    }
}

// ---------------- final decoder: mma.sync bf16 hi/lo, 128x128 tiles, 512 threads ----------------
#define ROWB 272
#define BUF_SZ (128 * ROWB)
#define SM_HI_I 0
#define SM_LO_I (BUF_SZ)
#define SM_HI_J (2 * BUF_SZ)
#define SM_LO_J (3 * BUF_SZ)
#define SM_TOTAL (4 * BUF_SZ)

__global__ void __launch_bounds__(512) final_kernel(float* __restrict__ out, int n) {
    extern __shared__ char smem_raw[];
    int tid = threadIdx.x;
    int w = tid >> 5, lane = tid & 31;

    int p = blockIdx.x;
    int bi = (int)((sqrtf(8.0f * (float)p + 1.0f) - 1.0f) * 0.5f);
    while ((bi + 1) * (bi + 2) / 2 <= p) bi++;
    while (bi * (bi + 1) / 2 > p) bi--;
    int bj = p - bi * (bi + 1) / 2;
    int i0 = bi * 128, j0 = bj * 128;

    const uint4 zz = make_uint4(0u, 0u, 0u, 0u);
    for (int c = tid; c < 2048; c += 512) {
        int row = c >> 4, seg = c & 15;
        int off = row * ROWB + seg * 16;
        int gi = i0 + row, gj = j0 + row;
        uint4 hi_i = zz, lo_i = zz, hi_j = zz, lo_j = zz;
        if (gi < n) {
            hi_i = *(const uint4*)&g_zhi[gi * H2 + seg * 8];
            lo_i = *(const uint4*)&g_zlo[gi * H2 + seg * 8];
        }
        if (gj < n) {
            hi_j = *(const uint4*)&g_zhi[gj * H2 + seg * 8];
            lo_j = *(const uint4*)&g_zlo[gj * H2 + seg * 8];
        }
        *(uint4*)(smem_raw + SM_HI_I + off) = hi_i;
        *(uint4*)(smem_raw + SM_LO_I + off) = lo_i;
        *(uint4*)(smem_raw + SM_HI_J + off) = hi_j;
        *(uint4*)(smem_raw + SM_LO_J + off) = lo_j;
    }
    __syncthreads();

    uint32_t smb = smem_u32(smem_raw);
    int warp_m = w & 1, warp_n = w >> 1;       // 2 x 8 warp grid; warp tile 64m x 16n
    uint32_t aoffA = (uint32_t)((warp_m * 64 + (lane & 15)) * ROWB + (lane >> 4) * 16);
    uint32_t aoffB = (uint32_t)((warp_n * 16 + (lane & 7)) * ROWB + ((lane >> 3) & 1) * 16);

    float acc[4][2][4] = {};   // [mfrag][nfrag][reg]

    for (int ks = 0; ks < 8; ks++) {
        uint32_t k2 = (uint32_t)(ks * 32);
        uint32_t Ahi[4][4], Bhi[2][2], Blo[2][2];
#pragma unroll
        for (int mf = 0; mf < 4; mf++)
            ldsm_x4(Ahi[mf], smb + SM_HI_I + aoffA + mf * (16 * ROWB) + k2);
#pragma unroll
        for (int nf = 0; nf < 2; nf++) {
            ldsm_x2(Bhi[nf], smb + SM_HI_J + aoffB + nf * (8 * ROWB) + k2);
            ldsm_x2(Blo[nf], smb + SM_LO_J + aoffB + nf * (8 * ROWB) + k2);
        }
#pragma unroll
        for (int mf = 0; mf < 4; mf++)
#pragma unroll
            for (int nf = 0; nf < 2; nf++) {
                mma_bf16(acc[mf][nf], Ahi[mf], Bhi[nf]);
                mma_bf16(acc[mf][nf], Ahi[mf], Blo[nf]);
            }
        uint32_t Alo[4][4];
#pragma unroll
        for (int mf = 0; mf < 4; mf++)
            ldsm_x4(Alo[mf], smb + SM_LO_I + aoffA + mf * (16 * ROWB) + k2);
#pragma unroll
        for (int mf = 0; mf < 4; mf++)
#pragma unroll
            for (int nf = 0; nf < 2; nf++)
                mma_bf16(acc[mf][nf], Alo[mf], Bhi[nf]);
    }

#pragma unroll
    for (int mf = 0; mf < 4; mf++)
#pragma unroll
        for (int nf = 0; nf < 2; nf++)
#pragma unroll
            for (int r = 0; r < 4; r++)
                acc[mf][nf][r] = sigm(acc[mf][nf][r]);

    int g = lane >> 2, q = lane & 3;

    // direct store: out[i][j]
#pragma unroll
    for (int mf = 0; mf < 4; mf++) {
#pragma unroll
        for (int rr = 0; rr < 2; rr++) {
            int i = i0 + warp_m * 64 + mf * 16 + g + rr * 8;
            if (i < n) {
#pragma unroll
                for (int nf = 0; nf < 2; nf++) {
                    int j = j0 + warp_n * 16 + nf * 8 + q * 2;
                    if (j + 1 < n) {
                        *(float2*)&out[(size_t)i * n + j] =
                            make_float2(acc[mf][nf][rr * 2], acc[mf][nf][rr * 2 + 1]);
                    } else if (j < n) {
                        out[(size_t)i * n + j] = acc[mf][nf][rr * 2];
                    }
                }
            }
        }
    }

    // mirror store via smem transpose
    if (bi != bj) {
        __syncthreads();
        float* smt = (float*)smem_raw;   // [128][132] fp32, 67584B < SM_TOTAL
#pragma unroll
        for (int mf = 0; mf < 4; mf++) {
            int irel_base = warp_m * 64 + mf * 16 + g;
#pragma unroll
            for (int nf = 0; nf < 2; nf++) {
                int jrel = warp_n * 16 + nf * 8 + q * 2;
                smt[(jrel)     * 132 + irel_base]     = acc[mf][nf][0];
                smt[(jrel + 1) * 132 + irel_base]     = acc[mf][nf][1];
                smt[(jrel)     * 132 + irel_base + 8] = acc[mf][nf][2];
                smt[(jrel + 1) * 132 + irel_base + 8] = acc[mf][nf][3];
            }
        }
        __syncthreads();
        for (int c = tid; c < 128 * 32; c += 512) {
            int jr = c >> 5;
            int i4 = (c & 31) * 4;
            int gi = i0 + i4;
            size_t off = (size_t)(j0 + jr) * n + gi;
            float4 v = *(const float4*)&smt[jr * 132 + i4];
            if (gi + 3 < n) {
                *(float4*)&out[off] = v;
            } else {
                float a[4] = {v.x, v.y, v.z, v.w};
#pragma unroll
                for (int u = 0; u < 4; u++)
                    if (gi + u < n) out[off + u] = a[u];
            }
        }
    }
}

// ---------------- launch ----------------
extern "C" void kernel_launch(void* const* d_in, const int* in_sizes, int n_in,
                              void* d_out, int out_size) {
    const float* features = (const float*)d_in[0];
    const int*   src      = (const int*)d_in[1];
    const int*   dst      = (const int*)d_in[2];
    const float* noise    = (const float*)d_in[3];
    const float* W1       = (const float*)d_in[4];
    const float* b1       = (const float*)d_in[5];
    const float* W2       = (const float*)d_in[6];
    const float* b2       = (const float*)d_in[7];
    const float* W3       = (const float*)d_in[8];
    const float* b3       = (const float*)d_in[9];
    int N = in_sizes[0] / IN_DIM;
    int E = in_sizes[1];
    float* out = (float*)d_out;

    cudaFuncSetAttribute(final_kernel, cudaFuncAttributeMaxDynamicSharedMemorySize, SM_TOTAL);
    cudaFuncSetAttribute(gemm1_hmma, cudaFuncAttributeMaxDynamicSharedMemorySize, G_TOTAL);
    cudaFuncSetAttribute(gemm23_hmma, cudaFuncAttributeMaxDynamicSharedMemorySize, G_TOTAL);

    zero_kernel<<<(N + 255) / 256, 256>>>(N);
    degree_kernel<<<(E + 255) / 256, 256>>>(src, dst, E);
    rs_alloc_kernel<<<(N + 255) / 256, 256>>>(N);
    perm_kernel<<<(E + 255) / 256, 256>>>(src, dst, E);
    convw_kernel<<<(H1 * IN_DIM + H1 * H1 + 255) / 256, 256>>>(W1, W2, W3);

    dim3 gg((N + 127) / 128, 2);
    gemm1_hmma<<<gg, 256, G_TOTAL>>>(features, N);
    agg1_kernel<<<N, 128>>>(b1);
    gemm23_hmma<<<gg, 256, G_TOTAL>>>(N);
    aggz_kernel<<<N, 128>>>(b2, b3, noise);

    int T = (N + 127) / 128;
    final_kernel<<<T * (T + 1) / 2, 512, SM_TOTAL>>>(out, N);
}

// round 12
// speedup vs baseline: 2.1934x; 1.0160x over previous
#include <cuda_runtime.h>
#include <cuda_bf16.h>
#include <cstdint>

#define MAXN 10000
#define MAXE 320000
#define IN_DIM 512
#define H1 256
#define H2 128

// ---------------- scratch (device globals; no allocation allowed) ----------------
__device__ int   g_deg_out[MAXN];
__device__ int   g_deg_in[MAXN];
__device__ int   g_cnt[MAXN];
__device__ int   g_alloc;
__device__ float g_rs_out[MAXN];
__device__ float g_rs_in[MAXN];
__device__ int   g_row_off[MAXN];
__device__ int   g_perm_src[MAXE];
__device__ float g_y1[MAXN * H1];    // (x*rs_out) @ W1
__device__ float g_y23[MAXN * H1];   // (h*rs_out) @ [W2|W3]
__device__ __align__(16) __nv_bfloat16 g_ha_hi[MAXN * H1];  // (h*rs_out) bf16 hi
__device__ __align__(16) __nv_bfloat16 g_ha_lo[MAXN * H1];  // (h*rs_out) bf16 lo
__device__ __align__(16) __nv_bfloat16 g_w1t_hi[H1 * IN_DIM];   // W1^T [256][512]
__device__ __align__(16) __nv_bfloat16 g_w1t_lo[H1 * IN_DIM];
__device__ __align__(16) __nv_bfloat16 g_w23t_hi[H1 * H1];      // [W2|W3]^T [256][256]
__device__ __align__(16) __nv_bfloat16 g_w23t_lo[H1 * H1];
__device__ __align__(16) __nv_bfloat16 g_zhi[MAXN * H2];
__device__ __align__(16) __nv_bfloat16 g_zlo[MAXN * H2];

// ---------------- helpers ----------------
__device__ __forceinline__ float sigm(float x) {
    return 1.0f / (1.0f + __expf(-x));
}
__device__ __forceinline__ void bsplit(float v, __nv_bfloat16& hi, __nv_bfloat16& lo) {
    hi = __float2bfloat16(v);
    lo = __float2bfloat16(v - __bfloat162float(hi));
}
__device__ __forceinline__ uint32_t smem_u32(const void* p) {
    uint32_t a;
    asm("{ .reg .u64 t; cvta.to.shared.u64 t, %1; cvt.u32.u64 %0, t; }" : "=r"(a) : "l"(p));
    return a;
}
__device__ __forceinline__ void ldsm_x4(uint32_t a[4], uint32_t addr) {
    asm volatile("ldmatrix.sync.aligned.m8n8.x4.shared.b16 {%0,%1,%2,%3}, [%4];"
        : "=r"(a[0]), "=r"(a[1]), "=r"(a[2]), "=r"(a[3]) : "r"(addr));
}
__device__ __forceinline__ void ldsm_x2(uint32_t b[2], uint32_t addr) {
    asm volatile("ldmatrix.sync.aligned.m8n8.x2.shared.b16 {%0,%1}, [%2];"
        : "=r"(b[0]), "=r"(b[1]) : "r"(addr));
}
__device__ __forceinline__ void mma_bf16(float d[4], const uint32_t a[4], const uint32_t b[2]) {
    asm volatile("mma.sync.aligned.m16n8k16.row.col.f32.bf16.bf16.f32 "
        "{%0,%1,%2,%3}, {%4,%5,%6,%7}, {%8,%9}, {%0,%1,%2,%3};"
        : "+f"(d[0]), "+f"(d[1]), "+f"(d[2]), "+f"(d[3])
        : "r"(a[0]), "r"(a[1]), "r"(a[2]), "r"(a[3]), "r"(b[0]), "r"(b[1]));
}
__device__ __forceinline__ uint32_t pack_bf2(__nv_bfloat16 a, __nv_bfloat16 b) {
    __nv_bfloat162 v(a, b);
    return *(uint32_t*)&v;
}

// ---------------- small setup kernels ----------------
__global__ void zero_kernel(int n) {
    int i = blockIdx.x * blockDim.x + threadIdx.x;
    if (i < n) { g_deg_out[i] = 0; g_deg_in[i] = 0; g_cnt[i] = 0; }
    if (i == 0) g_alloc = 0;
}

__global__ void degree_kernel(const int* __restrict__ src, const int* __restrict__ dst, int e) {
    int i = blockIdx.x * blockDim.x + threadIdx.x;
    if (i < e) {
        atomicAdd(&g_deg_out[src[i]], 1);
        atomicAdd(&g_deg_in[dst[i]], 1);
    }
}

__global__ void rs_alloc_kernel(int n) {
    int i = blockIdx.x * blockDim.x + threadIdx.x;
    if (i < n) {
        int dIn = g_deg_in[i];
        g_rs_out[i] = rsqrtf(fmaxf((float)g_deg_out[i], 1.0f));
        g_rs_in[i]  = rsqrtf(fmaxf((float)dIn, 1.0f));
        g_row_off[i] = atomicAdd(&g_alloc, dIn);
    }
}

__global__ void perm_kernel(const int* __restrict__ src, const int* __restrict__ dst, int e) {
    int i = blockIdx.x * blockDim.x + threadIdx.x;
    if (i < e) {
        int d = dst[i];
        int pos = atomicAdd(&g_cnt[d], 1);
        g_perm_src[g_row_off[d] + pos] = src[i];
    }
}

// one-shot weight transpose + bf16 hi/lo split
__global__ void convw_kernel(const float* __restrict__ W1, const float* __restrict__ W2,
                             const float* __restrict__ W3) {
    int idx = blockIdx.x * blockDim.x + threadIdx.x;
    if (idx < H1 * IN_DIM) {
        int nn = idx >> 9, k = idx & 511;
        __nv_bfloat16 hi, lo;
        bsplit(W1[k * H1 + nn], hi, lo);
        g_w1t_hi[idx] = hi;
        g_w1t_lo[idx] = lo;
    } else {
        int j = idx - H1 * IN_DIM;
        if (j < H1 * H1) {
            int nn = j >> 8, k = j & 255;
            float v = (nn < H2) ? W2[k * H2 + nn] : W3[k * H2 + (nn - H2)];
            __nv_bfloat16 hi, lo;
            bsplit(v, hi, lo);
            g_w23t_hi[j] = hi;
            g_w23t_lo[j] = lo;
        }
    }
}

// ---------------- HMMA GEMM smem geometry ----------------
#define ROWB_G 144
#define GBUF (128 * ROWB_G)
#define GA_HI 0
#define GA_LO GBUF
#define GB_HI (2 * GBUF)
#define GB_LO (3 * GBUF)
#define G_TOTAL (4 * GBUF)             // 73728

// ---------------- GEMM1: y1 = (X*rs_out) @ W1 ----------------
__global__ void __launch_bounds__(256) gemm1_hmma(const float* __restrict__ X, int M) {
    extern __shared__ char smem_raw[];
    int tid = threadIdx.x;
    int w = tid >> 5, lane = tid & 31;
    int m0 = blockIdx.x * 128, n0 = blockIdx.y * 128;
    uint32_t smb = smem_u32(smem_raw);
    int warp_m = w & 1, warp_n = w >> 1;
    uint32_t aoffA = (uint32_t)((warp_m * 64 + (lane & 15)) * ROWB_G + (lane >> 4) * 16);
    uint32_t aoffB = (uint32_t)((warp_n * 32 + (lane & 7)) * ROWB_G + ((lane >> 3) & 1) * 16);

    float acc[4][4][4] = {};

    for (int ch = 0; ch < IN_DIM / 64; ch++) {
        int k0 = ch * 64;
        __syncthreads();
#pragma unroll
        for (int q = 0; q < 8; q++) {
            int idx = q * 256 + tid;
            int row = idx >> 4, c4 = (idx & 15) * 4;
            int gi = m0 + row;
            float4 v = make_float4(0.f, 0.f, 0.f, 0.f);
            float ro = 0.f;
            if (gi < M) { v = *(const float4*)&X[gi * IN_DIM + k0 + c4]; ro = g_rs_out[gi]; }
            __nv_bfloat16 h0, l0, h1, l1, h2, l2, h3, l3;
            bsplit(v.x * ro, h0, l0); bsplit(v.y * ro, h1, l1);
            bsplit(v.z * ro, h2, l2); bsplit(v.w * ro, h3, l3);
            int off = row * ROWB_G + c4 * 2;
            *(uint2*)(smem_raw + GA_HI + off) = make_uint2(pack_bf2(h0, h1), pack_bf2(h2, h3));
            *(uint2*)(smem_raw + GA_LO + off) = make_uint2(pack_bf2(l0, l1), pack_bf2(l2, l3));
        }
#pragma unroll
        for (int q = 0; q < 4; q++) {
            int idx = q * 256 + tid;
            int row = idx >> 3, seg = (idx & 7);
            int off = row * ROWB_G + seg * 16;
            *(uint4*)(smem_raw + GB_HI + off) = *(const uint4*)&g_w1t_hi[(n0 + row) * IN_DIM + k0 + seg * 8];
            *(uint4*)(smem_raw + GB_LO + off) = *(const uint4*)&g_w1t_lo[(n0 + row) * IN_DIM + k0 + seg * 8];
        }
        __syncthreads();
#pragma unroll
        for (int ks = 0; ks < 4; ks++) {
            uint32_t k2 = (uint32_t)(ks * 32);
            uint32_t Ahi[4][4], Bhi[4][2], Blo[4][2];
#pragma unroll
            for (int mf = 0; mf < 4; mf++)
                ldsm_x4(Ahi[mf], smb + GA_HI + aoffA + mf * (16 * ROWB_G) + k2);
#pragma unroll
            for (int nf = 0; nf < 4; nf++) {
                ldsm_x2(Bhi[nf], smb + GB_HI + aoffB + nf * (8 * ROWB_G) + k2);
                ldsm_x2(Blo[nf], smb + GB_LO + aoffB + nf * (8 * ROWB_G) + k2);
            }
#pragma unroll
            for (int mf = 0; mf < 4; mf++)
#pragma unroll
                for (int nf = 0; nf < 4; nf++) {
                    mma_bf16(acc[mf][nf], Ahi[mf], Bhi[nf]);
                    mma_bf16(acc[mf][nf], Ahi[mf], Blo[nf]);
                }
            uint32_t Alo[4][4];
#pragma unroll
            for (int mf = 0; mf < 4; mf++)
                ldsm_x4(Alo[mf], smb + GA_LO + aoffA + mf * (16 * ROWB_G) + k2);
#pragma unroll
            for (int mf = 0; mf < 4; mf++)
#pragma unroll
                for (int nf = 0; nf < 4; nf++)
                    mma_bf16(acc[mf][nf], Alo[mf], Bhi[nf]);
        }
    }
    int g = lane >> 2, q = lane & 3;
#pragma unroll
    for (int mf = 0; mf < 4; mf++)
#pragma unroll
        for (int rr = 0; rr < 2; rr++) {
            int i = m0 + warp_m * 64 + mf * 16 + g + rr * 8;
            if (i < M) {
#pragma unroll
                for (int nf = 0; nf < 4; nf++) {
                    int j = n0 + warp_n * 32 + nf * 8 + q * 2;
                    *(float2*)&g_y1[i * H1 + j] =
                        make_float2(acc[mf][nf][rr * 2], acc[mf][nf][rr * 2 + 1]);
                }
            }
        }
}

// ---------------- GEMM23: y23 = (h*rs_out) @ [W2|W3] ----------------
__global__ void __launch_bounds__(256) gemm23_hmma(int M) {
    extern __shared__ char smem_raw[];
    int tid = threadIdx.x;
    int w = tid >> 5, lane = tid & 31;
    int m0 = blockIdx.x * 128, n0 = blockIdx.y * 128;
    uint32_t smb = smem_u32(smem_raw);
    int warp_m = w & 1, warp_n = w >> 1;
    uint32_t aoffA = (uint32_t)((warp_m * 64 + (lane & 15)) * ROWB_G + (lane >> 4) * 16);
    uint32_t aoffB = (uint32_t)((warp_n * 32 + (lane & 7)) * ROWB_G + ((lane >> 3) & 1) * 16);

    float acc[4][4][4] = {};
    const uint4 zz = make_uint4(0u, 0u, 0u, 0u);

    for (int ch = 0; ch < H1 / 64; ch++) {
        int k0 = ch * 64;
        __syncthreads();
#pragma unroll
        for (int q = 0; q < 4; q++) {
            int idx = q * 256 + tid;
            int row = idx >> 3, seg = (idx & 7);
            int off = row * ROWB_G + seg * 16;
            int gi = m0 + row;
            uint4 ahi = zz, alo = zz;
            if (gi < M) {
                ahi = *(const uint4*)&g_ha_hi[gi * H1 + k0 + seg * 8];
                alo = *(const uint4*)&g_ha_lo[gi * H1 + k0 + seg * 8];
            }
            *(uint4*)(smem_raw + GA_HI + off) = ahi;
            *(uint4*)(smem_raw + GA_LO + off) = alo;
            *(uint4*)(smem_raw + GB_HI + off) = *(const uint4*)&g_w23t_hi[(n0 + row) * H1 + k0 + seg * 8];
            *(uint4*)(smem_raw + GB_LO + off) = *(const uint4*)&g_w23t_lo[(n0 + row) * H1 + k0 + seg * 8];
        }
        __syncthreads();
#pragma unroll
        for (int ks = 0; ks < 4; ks++) {
            uint32_t k2 = (uint32_t)(ks * 32);
            uint32_t Ahi[4][4], Bhi[4][2], Blo[4][2];
#pragma unroll
            for (int mf = 0; mf < 4; mf++)
                ldsm_x4(Ahi[mf], smb + GA_HI + aoffA + mf * (16 * ROWB_G) + k2);
#pragma unroll
            for (int nf = 0; nf < 4; nf++) {
                ldsm_x2(Bhi[nf], smb + GB_HI + aoffB + nf * (8 * ROWB_G) + k2);
                ldsm_x2(Blo[nf], smb + GB_LO + aoffB + nf * (8 * ROWB_G) + k2);
            }
#pragma unroll
            for (int mf = 0; mf < 4; mf++)
#pragma unroll
                for (int nf = 0; nf < 4; nf++) {
                    mma_bf16(acc[mf][nf], Ahi[mf], Bhi[nf]);
                    mma_bf16(acc[mf][nf], Ahi[mf], Blo[nf]);
                }
            uint32_t Alo[4][4];
#pragma unroll
            for (int mf = 0; mf < 4; mf++)
                ldsm_x4(Alo[mf], smb + GA_LO + aoffA + mf * (16 * ROWB_G) + k2);
#pragma unroll
            for (int mf = 0; mf < 4; mf++)
#pragma unroll
                for (int nf = 0; nf < 4; nf++)
                    mma_bf16(acc[mf][nf], Alo[mf], Bhi[nf]);
        }
    }
    int g = lane >> 2, q = lane & 3;
#pragma unroll
    for (int mf = 0; mf < 4; mf++)
#pragma unroll
        for (int rr = 0; rr < 2; rr++) {
            int i = m0 + warp_m * 64 + mf * 16 + g + rr * 8;
            if (i < M) {
#pragma unroll
                for (int nf = 0; nf < 4; nf++) {
                    int j = n0 + warp_n * 32 + nf * 8 + q * 2;
                    *(float2*)&g_y23[i * H1 + j] =
                        make_float2(acc[mf][nf][rr * 2], acc[mf][nf][rr * 2 + 1]);
                }
            }
        }
}

// ---------------- agg1: unroll-4 gather; h = relu(rs_in*sum + b1); emit (h*rs_out) bf16 ----------------
__global__ void agg1_kernel(const float* __restrict__ b1) {
    int d = blockIdx.x, t = threadIdx.x;
    int s = g_row_off[d], e = s + g_deg_in[d];
    const float2* Y = (const float2*)g_y1;
    float2 a0 = make_float2(0.f, 0.f), a1 = a0, a2 = a0, a3 = a0;
    int i = s;
    for (; i + 3 < e; i += 4) {
        int s0 = g_perm_src[i], s1 = g_perm_src[i + 1];
        int s2 = g_perm_src[i + 2], s3 = g_perm_src[i + 3];
        float2 v0 = Y[s0 * (H1 / 2) + t];
        float2 v1 = Y[s1 * (H1 / 2) + t];
        float2 v2 = Y[s2 * (H1 / 2) + t];
        float2 v3 = Y[s3 * (H1 / 2) + t];
        a0.x += v0.x; a0.y += v0.y;
        a1.x += v1.x; a1.y += v1.y;
        a2.x += v2.x; a2.y += v2.y;
        a3.x += v3.x; a3.y += v3.y;
    }
    for (; i < e; i++) {
        int sn = g_perm_src[i];
        float2 v = Y[sn * (H1 / 2) + t];
        a0.x += v.x; a0.y += v.y;
    }
    float ax = (a0.x + a1.x) + (a2.x + a3.x);
    float ay = (a0.y + a1.y) + (a2.y + a3.y);
    float ri = g_rs_in[d];
    float ro = g_rs_out[d];
    float h0 = fmaxf(ax * ri + b1[2 * t], 0.f) * ro;
    float h1 = fmaxf(ay * ri + b1[2 * t + 1], 0.f) * ro;
    __nv_bfloat16 hi0, lo0, hi1, lo1;
    bsplit(h0, hi0, lo0);
    bsplit(h1, hi1, lo1);
    ((uint32_t*)g_ha_hi)[d * (H1 / 2) + t] = pack_bf2(hi0, hi1);
    ((uint32_t*)g_ha_lo)[d * (H1 / 2) + t] = pack_bf2(lo0, lo1);
}

// ---------------- aggz: unroll-4 gather; z = (s0+b2) + noise*exp(s1+b3) ----------------
__global__ void aggz_kernel(const float* __restrict__ b2, const float* __restrict__ b3,
                            const float* __restrict__ noise) {
    __shared__ float sm[H1];
    int d = blockIdx.x, t = threadIdx.x;
    int s = g_row_off[d], e = s + g_deg_in[d];
    const float2* Y = (const float2*)g_y23;
    float2 a0 = make_float2(0.f, 0.f), a1 = a0, a2 = a0, a3 = a0;
    int i = s;
    for (; i + 3 < e; i += 4) {
        int s0 = g_perm_src[i], s1 = g_perm_src[i + 1];
        int s2 = g_perm_src[i + 2], s3 = g_perm_src[i + 3];
        float2 v0 = Y[s0 * (H1 / 2) + t];
        float2 v1 = Y[s1 * (H1 / 2) + t];
        float2 v2 = Y[s2 * (H1 / 2) + t];
        float2 v3 = Y[s3 * (H1 / 2) + t];
        a0.x += v0.x; a0.y += v0.y;
        a1.x += v1.x; a1.y += v1.y;
        a2.x += v2.x; a2.y += v2.y;
        a3.x += v3.x; a3.y += v3.y;
    }
    for (; i < e; i++) {
        int sn = g_perm_src[i];
        float2 v = Y[sn * (H1 / 2) + t];
        a0.x += v.x; a0.y += v.y;
    }
    float ax = (a0.x + a1.x) + (a2.x + a3.x);
    float ay = (a0.y + a1.y) + (a2.y + a3.y);
    float ri = g_rs_in[d];
    sm[2 * t] = ax * ri;
    sm[2 * t + 1] = ay * ri;
    __syncthreads();
    if (t < 64) {
#pragma unroll
        for (int q = 0; q < 2; q++) {
            int c = 2 * t + q;
            float mean = sm[c] + b2[c];
            float ls = sm[c + H2] + b3[c];
            float zv = mean + noise[d * H2 + c] * expf(ls);
            __nv_bfloat16 hi, lo;
            bsplit(zv, hi, lo);
            g_zhi[d * H2 + c] = hi;
            g_zlo[d * H2 + c] = lo;
        }
    }
}

// ---------------- final decoder: mma.sync bf16 hi/lo, 64x128 half-tiles, 2 CTA/SM ----------------
#define ROWB 272
#define IBUF (64 * ROWB)                 // 17408
#define JBUF (128 * ROWB)                // 34816
#define SM_HI_I 0
#define SM_LO_I (IBUF)
#define SM_HI_J (2 * IBUF)
#define SM_LO_J (2 * IBUF + JBUF)
#define SM_TOTAL (2 * IBUF + 2 * JBUF)   // 104448 -> 2 CTAs/SM

__global__ void __launch_bounds__(256) final_kernel(float* __restrict__ out, int n) {
    extern __shared__ char smem_raw[];
    int tid = threadIdx.x;
    int w = tid >> 5, lane = tid & 31;

    int x = blockIdx.x;
    int p = x >> 1, half = x & 1;
    int bi = (int)((sqrtf(8.0f * (float)p + 1.0f) - 1.0f) * 0.5f);
    while ((bi + 1) * (bi + 2) / 2 <= p) bi++;
    while (bi * (bi + 1) / 2 > p) bi--;
    int bj = p - bi * (bi + 1) / 2;
    int i0 = bi * 128 + half * 64;       // 64-row i half-tile
    int j0 = bj * 128;                   // 128-col j tile

    // ---- load tiles: j 128 rows, i 64 rows ----
    const uint4 zz = make_uint4(0u, 0u, 0u, 0u);
    for (int c = tid; c < 2048; c += 256) {
        int row = c >> 4, seg = c & 15;
        int off = row * ROWB + seg * 16;
        int gj = j0 + row;
        uint4 hi_j = zz, lo_j = zz;
        if (gj < n) {
            hi_j = *(const uint4*)&g_zhi[gj * H2 + seg * 8];
            lo_j = *(const uint4*)&g_zlo[gj * H2 + seg * 8];
        }
        *(uint4*)(smem_raw + SM_HI_J + off) = hi_j;
        *(uint4*)(smem_raw + SM_LO_J + off) = lo_j;
        if (row < 64) {
            int gi = i0 + row;
            uint4 hi_i = zz, lo_i = zz;
            if (gi < n) {
                hi_i = *(const uint4*)&g_zhi[gi * H2 + seg * 8];
                lo_i = *(const uint4*)&g_zlo[gi * H2 + seg * 8];
            }
            *(uint4*)(smem_raw + SM_HI_I + off) = hi_i;
            *(uint4*)(smem_raw + SM_LO_I + off) = lo_i;
        }
    }
    __syncthreads();

    uint32_t smb = smem_u32(smem_raw);
    int warp_m = w & 1, warp_n = w >> 1;      // 2 x 4 warp grid; warp tile 32m x 32n
    uint32_t aoffA = (uint32_t)((warp_m * 32 + (lane & 15)) * ROWB + (lane >> 4) * 16);
    uint32_t aoffB = (uint32_t)((warp_n * 32 + (lane & 7)) * ROWB + ((lane >> 3) & 1) * 16);

    float acc[2][4][4] = {};   // [mfrag][nfrag][reg]

    for (int ks = 0; ks < 8; ks++) {
        uint32_t k2 = (uint32_t)(ks * 32);
        uint32_t Ahi[2][4], Bhi[4][2], Blo[4][2];
#pragma unroll
        for (int mf = 0; mf < 2; mf++)
            ldsm_x4(Ahi[mf], smb + SM_HI_I + aoffA + mf * (16 * ROWB) + k2);
#pragma unroll
        for (int nf = 0; nf < 4; nf++) {
            ldsm_x2(Bhi[nf], smb + SM_HI_J + aoffB + nf * (8 * ROWB) + k2);
            ldsm_x2(Blo[nf], smb + SM_LO_J + aoffB + nf * (8 * ROWB) + k2);
        }
#pragma unroll
        for (int mf = 0; mf < 2; mf++)
#pragma unroll
            for (int nf = 0; nf < 4; nf++) {
                mma_bf16(acc[mf][nf], Ahi[mf], Bhi[nf]);
                mma_bf16(acc[mf][nf], Ahi[mf], Blo[nf]);
            }
        uint32_t Alo[2][4];
#pragma unroll
        for (int mf = 0; mf < 2; mf++)
            ldsm_x4(Alo[mf], smb + SM_LO_I + aoffA + mf * (16 * ROWB) + k2);
#pragma unroll
        for (int mf = 0; mf < 2; mf++)
#pragma unroll
            for (int nf = 0; nf < 4; nf++)
                mma_bf16(acc[mf][nf], Alo[mf], Bhi[nf]);
    }

#pragma unroll
    for (int mf = 0; mf < 2; mf++)
#pragma unroll
        for (int nf = 0; nf < 4; nf++)
#pragma unroll
            for (int r = 0; r < 4; r++)
                acc[mf][nf][r] = sigm(acc[mf][nf][r]);

    int g = lane >> 2, q = lane & 3;

    // direct store: out[i][j]
#pragma unroll
    for (int mf = 0; mf < 2; mf++) {
#pragma unroll
        for (int rr = 0; rr < 2; rr++) {
            int i = i0 + warp_m * 32 + mf * 16 + g + rr * 8;
            if (i < n) {
#pragma unroll
                for (int nf = 0; nf < 4; nf++) {
                    int j = j0 + warp_n * 32 + nf * 8 + q * 2;
                    if (j + 1 < n) {
                        *(float2*)&out[(size_t)i * n + j] =
                            make_float2(acc[mf][nf][rr * 2], acc[mf][nf][rr * 2 + 1]);
                    } else if (j < n) {
                        out[(size_t)i * n + j] = acc[mf][nf][rr * 2];
                    }
                }
            }
        }
    }

    // mirror store via smem transpose: out[j][i], smt[128 j][68 i] fp32 (34816B < SM_TOTAL)
    if (bi != bj) {
        __syncthreads();
        float* smt = (float*)smem_raw;
#pragma unroll
        for (int mf = 0; mf < 2; mf++) {
            int irel_base = warp_m * 32 + mf * 16 + g;
#pragma unroll
            for (int nf = 0; nf < 4; nf++) {
                int jrel = warp_n * 32 + nf * 8 + q * 2;
                smt[(jrel)     * 68 + irel_base]     = acc[mf][nf][0];
                smt[(jrel + 1) * 68 + irel_base]     = acc[mf][nf][1];
                smt[(jrel)     * 68 + irel_base + 8] = acc[mf][nf][2];
                smt[(jrel + 1) * 68 + irel_base + 8] = acc[mf][nf][3];
            }
        }
        __syncthreads();
        for (int c = tid; c < 128 * 16; c += 256) {
            int jr = c >> 4;
            int i4 = (c & 15) * 4;
            int gi = i0 + i4;
            size_t off = (size_t)(j0 + jr) * n + gi;
            float4 v = *(const float4*)&smt[jr * 68 + i4];
            if (gi + 3 < n) {
                *(float4*)&out[off] = v;
            } else {
                float a[4] = {v.x, v.y, v.z, v.w};
#pragma unroll
                for (int u = 0; u < 4; u++)
                    if (gi + u < n) out[off + u] = a[u];
            }
        }
    }
}

// ---------------- launch ----------------
extern "C" void kernel_launch(void* const* d_in, const int* in_sizes, int n_in,
                              void* d_out, int out_size) {
    const float* features = (const float*)d_in[0];
    const int*   src      = (const int*)d_in[1];
    const int*   dst      = (const int*)d_in[2];
    const float* noise    = (const float*)d_in[3];
    const float* W1       = (const float*)d_in[4];
    const float* b1       = (const float*)d_in[5];
    const float* W2       = (const float*)d_in[6];
    const float* b2       = (const float*)d_in[7];
    const float* W3       = (const float*)d_in[8];
    const float* b3       = (const float*)d_in[9];
    int N = in_sizes[0] / IN_DIM;
    int E = in_sizes[1];
    float* out = (float*)d_out;

    cudaFuncSetAttribute(final_kernel, cudaFuncAttributeMaxDynamicSharedMemorySize, SM_TOTAL);
    cudaFuncSetAttribute(gemm1_hmma, cudaFuncAttributeMaxDynamicSharedMemorySize, G_TOTAL);
    cudaFuncSetAttribute(gemm23_hmma, cudaFuncAttributeMaxDynamicSharedMemorySize, G_TOTAL);

    zero_kernel<<<(N + 255) / 256, 256>>>(N);
    degree_kernel<<<(E + 255) / 256, 256>>>(src, dst, E);
    rs_alloc_kernel<<<(N + 255) / 256, 256>>>(N);
    perm_kernel<<<(E + 255) / 256, 256>>>(src, dst, E);
    convw_kernel<<<(H1 * IN_DIM + H1 * H1 + 255) / 256, 256>>>(W1, W2, W3);

    dim3 gg((N + 127) / 128, 2);
    gemm1_hmma<<<gg, 256, G_TOTAL>>>(features, N);
    agg1_kernel<<<N, 128>>>(b1);
    gemm23_hmma<<<gg, 256, G_TOTAL>>>(N);
    aggz_kernel<<<N, 128>>>(b2, b3, noise);

    int T = (N + 127) / 128;
    final_kernel<<<T * (T + 1), 256, SM_TOTAL>>>(out, N);
}